// round 5
// baseline (speedup 1.0000x reference)
#include <cuda_runtime.h>
#include <math.h>
#include <stddef.h>

// Problem constants
#define BATCH 4
#define HH 48
#define WW 48
#define DD 64
#define HC 46                 // valid patch grid
#define CC 2116               // HC*HC candidate patches
#define MM 2304               // HH*WW locations
#define TEMPR 50.0f

// Scratch (device globals -- no runtime allocation allowed)
static __device__ float g_E [(size_t)BATCH * MM * MM];   // E Gram, then S (85 MB)
static __device__ float g_DS[(size_t)BATCH * MM * CC];   // CA (78 MB)
static __device__ float g_bg [BATCH * MM * DD];          // g_in * mask
static __device__ float g_sg [BATCH * MM];               // per-pixel sum g^2
static __device__ float g_sbg[BATCH * MM];               // per-pixel sum bg^2
static __device__ float g_wwd[BATCH * MM];               // 3x3 box sum (same pad) of g_sg
static __device__ float g_k1d[BATCH * CC];               // 3x3 box sum (valid) of g_sbg
static __device__ float g_ACL[BATCH * MM * DD];

// ---------------------------------------------------------------------------
// Kernel 0a: bg = g_in * mask ; per-pixel sums of squares
__global__ void prep_kernel(const float* __restrict__ gin, const float* __restrict__ mask) {
    int p = blockIdx.x;
    int d = threadIdx.x;
    float mv = mask[p];
    float g  = gin[p * DD + d];
    float bgv = g * mv;
    g_bg[p * DD + d] = bgv;
    __shared__ float s1[DD];
    __shared__ float s2[DD];
    s1[d] = g * g;
    s2[d] = bgv * bgv;
    __syncthreads();
    #pragma unroll
    for (int s = 32; s > 0; s >>= 1) {
        if (d < s) { s1[d] += s1[d + s]; s2[d] += s2[d + s]; }
        __syncthreads();
    }
    if (d == 0) { g_sg[p] = s1[0]; g_sbg[p] = s2[0]; }
}

// Kernel 0b: box sums -> wwd (same pad) and k1d (valid)
__global__ void boxsum_kernel() {
    int idx = blockIdx.x * blockDim.x + threadIdx.x;
    if (idx < BATCH * MM) {
        int b = idx / MM, m = idx - b * MM;
        int y = m / WW, x = m - y * WW;
        float s = 0.f;
        #pragma unroll
        for (int dy = 0; dy < 3; dy++)
            #pragma unroll
            for (int dx = 0; dx < 3; dx++) {
                int yy = y + dy - 1, xx = x + dx - 1;
                if (yy >= 0 && yy < HH && xx >= 0 && xx < WW)
                    s += g_sg[(b * HH + yy) * WW + xx];
            }
        g_wwd[idx] = s;
    } else if (idx < BATCH * MM + BATCH * CC) {
        int id2 = idx - BATCH * MM;
        int b = id2 / CC, j = id2 - b * CC;
        int jy = j / HC, jx = j - jy * HC;
        float s = 0.f;
        #pragma unroll
        for (int dy = 0; dy < 3; dy++)
            #pragma unroll
            for (int dx = 0; dx < 3; dx++)
                s += g_sbg[(b * HH + jy + dy) * WW + jx + dx];
        g_k1d[id2] = s;
    }
}

// ---------------------------------------------------------------------------
// gemmE (SYRK form): G = gin @ gin^T is symmetric; E[p,q] = G[p,q]*mask[q].
// Compute only lower-triangular tiles (i >= j), write the tile and (if i!=j)
// its transpose with the p-side mask.  mask in {0,1} => bit-exact vs old path.
// 64x64 tile, BK=16, 256 threads, 4x4 microtile.
#define NTILE (MM / 64)                       // 36
#define NPAIR (NTILE * (NTILE + 1) / 2)       // 666
__global__ __launch_bounds__(256) void gemmE_syrk_kernel(const float* __restrict__ gin,
                                                         const float* __restrict__ mask) {
    __shared__ float As[16][64];
    __shared__ float Bs[16][64];
    int b = blockIdx.y;
    int t = blockIdx.x;
    // triangular index: t -> (i, j), j <= i
    int i = (int)((sqrtf(8.f * t + 1.f) - 1.f) * 0.5f);
    while ((i + 1) * (i + 2) / 2 <= t) i++;
    while (i * (i + 1) / 2 > t) i--;
    int j = t - i * (i + 1) / 2;
    int p0 = i * 64;
    int q0 = j * 64;

    int tid = threadIdx.x;
    int lk = (tid & 3) * 4;
    int lr = tid >> 2;
    int ty = tid >> 4, tx = tid & 15;

    const float* A = gin + (size_t)b * MM * DD;

    float acc[4][4];
    #pragma unroll
    for (int ii = 0; ii < 4; ii++)
        #pragma unroll
        for (int jj = 0; jj < 4; jj++) acc[ii][jj] = 0.f;

    #pragma unroll
    for (int k0 = 0; k0 < DD; k0 += 16) {
        float4 va = *(const float4*)(A + (p0 + lr) * DD + k0 + lk);
        As[lk + 0][lr] = va.x; As[lk + 1][lr] = va.y;
        As[lk + 2][lr] = va.z; As[lk + 3][lr] = va.w;
        float4 vb = *(const float4*)(A + (q0 + lr) * DD + k0 + lk);
        Bs[lk + 0][lr] = vb.x; Bs[lk + 1][lr] = vb.y;
        Bs[lk + 2][lr] = vb.z; Bs[lk + 3][lr] = vb.w;
        __syncthreads();
        #pragma unroll
        for (int k = 0; k < 16; k++) {
            float4 a4 = *(const float4*)(&As[k][ty * 4]);
            float4 b4 = *(const float4*)(&Bs[k][tx * 4]);
            float av[4] = {a4.x, a4.y, a4.z, a4.w};
            float bv[4] = {b4.x, b4.y, b4.z, b4.w};
            #pragma unroll
            for (int ii = 0; ii < 4; ii++)
                #pragma unroll
                for (int jj = 0; jj < 4; jj++) acc[ii][jj] += av[ii] * bv[jj];
        }
        __syncthreads();
    }

    float* Eb = g_E + (size_t)b * MM * MM;
    const float* mb = mask + b * MM;

    // normal write: E[p0+r, q0+c] = acc[r][c] * mask[q0+c]
    float mq[4];
    #pragma unroll
    for (int c = 0; c < 4; c++) mq[c] = mb[q0 + tx * 4 + c];
    #pragma unroll
    for (int r = 0; r < 4; r++) {
        float4 v;
        v.x = acc[r][0] * mq[0]; v.y = acc[r][1] * mq[1];
        v.z = acc[r][2] * mq[2]; v.w = acc[r][3] * mq[3];
        *(float4*)(Eb + (size_t)(p0 + ty * 4 + r) * MM + q0 + tx * 4) = v;
    }

    if (i != j) {
        // mirror write: E[q0+c, p0+r] = acc[r][c] * mask[p0+r]
        float mp[4];
        #pragma unroll
        for (int r = 0; r < 4; r++) mp[r] = mb[p0 + ty * 4 + r];
        #pragma unroll
        for (int c = 0; c < 4; c++) {
            float4 v;
            v.x = acc[0][c] * mp[0]; v.y = acc[1][c] * mp[1];
            v.z = acc[2][c] * mp[2]; v.w = acc[3][c] * mp[3];
            *(float4*)(Eb + (size_t)(q0 + tx * 4 + c) * MM + p0 + ty * 4) = v;
        }
    }
}

// ---------------------------------------------------------------------------
// Block-wide sum over 256 threads via shuffle + 8-slot smem.
__device__ __forceinline__ float block_sum256(float v, float* red) {
    int tid = threadIdx.x;
    #pragma unroll
    for (int o = 16; o > 0; o >>= 1) v += __shfl_xor_sync(0xffffffffu, v, o);
    __syncthreads();                 // protect red from previous use
    if ((tid & 31) == 0) red[tid >> 5] = v;
    __syncthreads();
    float tot = red[0] + red[1] + red[2] + red[3] + red[4] + red[5] + red[6] + red[7];
    return tot;
}

// ---------------------------------------------------------------------------
// Fused DS + tanh-normalized softmax.  One CTA per output row m.
// All 9 tap addresses = base + qb + (dy*48+dx)*(MM+1)  (compile-time tap consts).
__global__ __launch_bounds__(256) void ds_softmax_kernel() {
    __shared__ float red[8];
    int row = blockIdx.x;
    int b = row / MM, m = row - b * MM;
    int y = m / WW, x = m - y * WW;
    int tid = threadIdx.x;

    const float* Eb = g_E + (size_t)b * MM * MM;
    const float* base = Eb + (ptrdiff_t)((y - 1) * WW + (x - 1)) * MM;
    float wv = g_wwd[row];
    const float* k1 = g_k1d + b * CC;

    bool tvy[3], tvx[3];
    #pragma unroll
    for (int t = 0; t < 3; t++) {
        tvy[t] = (unsigned)(y + t - 1) < (unsigned)HH;
        tvx[t] = (unsigned)(x + t - 1) < (unsigned)WW;
    }
    bool interior = tvy[0] && tvy[2] && tvx[0] && tvx[2];

    float v[9];
    float s = 0.f;

    if (interior) {
        #pragma unroll
        for (int i = 0; i < 9; i++) {
            int n = tid + 256 * i;
            if (n < CC) {
                int jy = n / HC, jx = n - jy * HC;
                const float* p = base + (jy * WW + jx);
                float cs = 0.f;
                #pragma unroll
                for (int dy = 0; dy < 3; dy++)
                    #pragma unroll
                    for (int dx = 0; dx < 3; dx++)
                        cs += p[(dy * WW + dx) * (MM + 1)];
                float val = fmaf(-2.f, cs, k1[n] + wv);
                v[i] = val;
                s += val;
            } else v[i] = 0.f;
        }
    } else {
        #pragma unroll
        for (int i = 0; i < 9; i++) {
            int n = tid + 256 * i;
            if (n < CC) {
                int jy = n / HC, jx = n - jy * HC;
                const float* p = base + (jy * WW + jx);
                float cs = 0.f;
                #pragma unroll
                for (int dy = 0; dy < 3; dy++)
                    #pragma unroll
                    for (int dx = 0; dx < 3; dx++)
                        if (tvy[dy] && tvx[dx])
                            cs += p[(dy * WW + dx) * (MM + 1)];
                float val = fmaf(-2.f, cs, k1[n] + wv);
                v[i] = val;
                s += val;
            } else v[i] = 0.f;
        }
    }

    float mu = block_sum256(s, red) * (1.0f / CC);

    float s2 = 0.f;
    #pragma unroll
    for (int i = 0; i < 9; i++) {
        int n = tid + 256 * i;
        if (n < CC) { float d = v[i] - mu; s2 = fmaf(d, d, s2); }
    }
    float isd = rsqrtf(block_sum256(s2, red) * (1.0f / CC));

    // e = exp(-TEMP*tanh(w)) = exp(100/(e^{2w}+1) - 50),  w=(v-mu)*isd
    float se = 0.f;
    #pragma unroll
    for (int i = 0; i < 9; i++) {
        int n = tid + 256 * i;
        if (n < CC) {
            float w = (v[i] - mu) * isd;
            float u = __expf(2.f * w);
            float e = __expf(__fdividef(100.f, u + 1.f) - 50.f);
            v[i] = e;
            se += e;
        }
    }
    float inv = 1.0f / block_sum256(se, red);

    float* rp = g_DS + (size_t)row * CC;
    #pragma unroll
    for (int i = 0; i < 9; i++) {
        int n = tid + 256 * i;
        if (n < CC) rp[n] = v[i] * inv;
    }
}

// ---------------------------------------------------------------------------
// S gather: S[b,m,q] = sum_{dy,dx} CA[(y+1-dy, x+1-dx), (qy-dy)*46 + (qx-dx)]
__global__ __launch_bounds__(256) void s_gather_kernel() {
    int row = blockIdx.x;
    int b = row / MM, m = row - b * MM;
    int y = m / WW, x = m - y * WW;
    int tid = threadIdx.x;

    const float* CAb = g_DS + (size_t)b * MM * CC;
    const float* basep = CAb + (ptrdiff_t)((y + 1) * WW + (x + 1)) * CC;

    bool tvy[3], tvx[3];
    #pragma unroll
    for (int t = 0; t < 3; t++) {
        tvy[t] = (unsigned)(y + 1 - t) < (unsigned)HH;
        tvx[t] = (unsigned)(x + 1 - t) < (unsigned)WW;
    }
    bool interior_m = tvy[2] && tvx[2] && tvy[0] && tvx[0]; // y,x in [1,46]

    float* Sout = g_E + (size_t)b * MM * MM + (size_t)m * MM;

    if (interior_m) {
        for (int q = tid; q < MM; q += 256) {
            int qy = q / WW, qx = q - qy * WW;
            const float* p = basep + (qy * HC + qx);
            float s = 0.f;
            if (qy >= 2 && qy <= 45 && qx >= 2 && qx <= 45) {
                #pragma unroll
                for (int dy = 0; dy < 3; dy++)
                    #pragma unroll
                    for (int dx = 0; dx < 3; dx++)
                        s += p[-(dy * (WW * CC + HC) + dx * (CC + 1))];
            } else {
                #pragma unroll
                for (int dy = 0; dy < 3; dy++)
                    #pragma unroll
                    for (int dx = 0; dx < 3; dx++)
                        if ((unsigned)(qy - dy) < (unsigned)HC &&
                            (unsigned)(qx - dx) < (unsigned)HC)
                            s += p[-(dy * (WW * CC + HC) + dx * (CC + 1))];
            }
            Sout[q] = s;
        }
    } else {
        for (int q = tid; q < MM; q += 256) {
            int qy = q / WW, qx = q - qy * WW;
            const float* p = basep + (qy * HC + qx);
            float s = 0.f;
            #pragma unroll
            for (int dy = 0; dy < 3; dy++)
                #pragma unroll
                for (int dx = 0; dx < 3; dx++)
                    if (tvy[dy] && tvx[dx] &&
                        (unsigned)(qy - dy) < (unsigned)HC &&
                        (unsigned)(qx - dx) < (unsigned)HC)
                        s += p[-(dy * (WW * CC + HC) + dx * (CC + 1))];
            Sout[q] = s;
        }
    }
}

// ---------------------------------------------------------------------------
// gemm_acl: acl[m,d] = sum_q S[m,q] * bg[q,d]; ACL = bg + acl/9*(1-mask).
__global__ __launch_bounds__(256) void gemm_acl_kernel(const float* __restrict__ mask) {
    __shared__ float As[16][64];
    __shared__ float Bs[16][64];
    int b  = blockIdx.y;
    int m0 = blockIdx.x * 64;
    int tid = threadIdx.x;
    int lk = (tid & 3) * 4;
    int lr = tid >> 2;
    int bj = tid >> 4, bd = (tid & 15) * 4;
    int ty = tid >> 4, tx = tid & 15;

    const float* Sb  = g_E  + (size_t)b * MM * MM;
    const float* bgb = g_bg + (size_t)b * MM * DD;

    float acc[4][4];
    #pragma unroll
    for (int i = 0; i < 4; i++)
        #pragma unroll
        for (int j = 0; j < 4; j++) acc[i][j] = 0.f;

    for (int k0 = 0; k0 < MM; k0 += 16) {
        float4 va = *(const float4*)(Sb + (size_t)(m0 + lr) * MM + k0 + lk);
        As[lk + 0][lr] = va.x; As[lk + 1][lr] = va.y;
        As[lk + 2][lr] = va.z; As[lk + 3][lr] = va.w;
        float4 vb = *(const float4*)(bgb + (k0 + bj) * DD + bd);
        *(float4*)(&Bs[bj][bd]) = vb;
        __syncthreads();
        #pragma unroll
        for (int k = 0; k < 16; k++) {
            float4 a4 = *(const float4*)(&As[k][ty * 4]);
            float4 b4 = *(const float4*)(&Bs[k][tx * 4]);
            float av[4] = {a4.x, a4.y, a4.z, a4.w};
            float bv[4] = {b4.x, b4.y, b4.z, b4.w};
            #pragma unroll
            for (int i = 0; i < 4; i++)
                #pragma unroll
                for (int j = 0; j < 4; j++) acc[i][j] += av[i] * bv[j];
        }
        __syncthreads();
    }

    #pragma unroll
    for (int i = 0; i < 4; i++) {
        int rowm = b * MM + m0 + ty * 4 + i;
        float om = (1.f - mask[rowm]) * (1.f / 9.f);
        #pragma unroll
        for (int j = 0; j < 4; j++) {
            int idx = rowm * DD + tx * 4 + j;
            g_ACL[idx] = g_bg[idx] + acc[i][j] * om;
        }
    }
}

// ---------------------------------------------------------------------------
// Final: out = elu(concat(g_in, ACL) @ W2 + b2).  4 rows x 64 cols per block.
__global__ __launch_bounds__(256) void final_kernel(const float* __restrict__ gin,
                                                    const float* __restrict__ W2,
                                                    const float* __restrict__ b2,
                                                    float* __restrict__ out) {
    __shared__ float sA[4][128];
    int r0 = blockIdx.x * 4;
    int tid = threadIdx.x;
    for (int idx = tid; idx < 512; idx += 256) {
        int r = idx >> 7, k = idx & 127;
        int row = r0 + r;
        sA[r][k] = (k < DD) ? gin[row * DD + k] : g_ACL[row * DD + (k - DD)];
    }
    __syncthreads();
    int r = tid >> 6, d = tid & 63;
    int row = r0 + r;
    float acc = b2[d];
    #pragma unroll 8
    for (int k = 0; k < 128; k++) acc += sA[r][k] * W2[k * DD + d];
    out[row * DD + d] = (acc > 0.f) ? acc : expm1f(acc);
}

// ---------------------------------------------------------------------------
extern "C" void kernel_launch(void* const* d_in, const int* in_sizes, int n_in,
                              void* d_out, int out_size) {
    const float* gin  = (const float*)d_in[0];
    const float* mask = (const float*)d_in[1];
    const float* W2   = (const float*)d_in[2];
    const float* b2   = (const float*)d_in[3];
    float* out = (float*)d_out;

    prep_kernel<<<BATCH * MM, DD>>>(gin, mask);
    int tot = BATCH * MM + BATCH * CC;
    boxsum_kernel<<<(tot + 255) / 256, 256>>>();
    gemmE_syrk_kernel<<<dim3(NPAIR, BATCH), 256>>>(gin, mask);
    ds_softmax_kernel<<<BATCH * MM, 256>>>();
    s_gather_kernel<<<BATCH * MM, 256>>>();
    gemm_acl_kernel<<<dim3(MM / 64, BATCH), 256>>>(mask);
    final_kernel<<<BATCH * MM / 4, 256>>>(gin, W2, b2, out);
}

// round 6
// speedup vs baseline: 1.3976x; 1.3976x over previous
#include <cuda_runtime.h>
#include <math.h>
#include <stddef.h>

// Problem constants
#define BATCH 4
#define HH 48
#define WW 48
#define DD 64
#define HC 46                 // valid patch grid
#define CC 2116               // HC*HC candidate patches
#define MM 2304               // HH*WW locations
#define TEMPR 50.0f

// Scratch (device globals -- no runtime allocation allowed)
static __device__ float g_E [(size_t)BATCH * MM * MM];   // E Gram, then S (85 MB)
static __device__ float g_DS[(size_t)BATCH * MM * CC];   // CA (78 MB)
static __device__ float g_bg [BATCH * MM * DD];          // g_in * mask
static __device__ float g_sg [BATCH * MM];               // per-pixel sum g^2
static __device__ float g_sbg[BATCH * MM];               // per-pixel sum bg^2
static __device__ float g_wwd[BATCH * MM];               // 3x3 box sum (same pad) of g_sg
static __device__ float g_k1d[BATCH * CC];               // 3x3 box sum (valid) of g_sbg
static __device__ float g_ACL[BATCH * MM * DD];

// ---------------------------------------------------------------------------
// Kernel 0a: bg = g_in * mask ; per-pixel sums of squares
__global__ void prep_kernel(const float* __restrict__ gin, const float* __restrict__ mask) {
    int p = blockIdx.x;
    int d = threadIdx.x;
    float mv = mask[p];
    float g  = gin[p * DD + d];
    float bgv = g * mv;
    g_bg[p * DD + d] = bgv;
    __shared__ float s1[DD];
    __shared__ float s2[DD];
    s1[d] = g * g;
    s2[d] = bgv * bgv;
    __syncthreads();
    #pragma unroll
    for (int s = 32; s > 0; s >>= 1) {
        if (d < s) { s1[d] += s1[d + s]; s2[d] += s2[d + s]; }
        __syncthreads();
    }
    if (d == 0) { g_sg[p] = s1[0]; g_sbg[p] = s2[0]; }
}

// Kernel 0b: box sums -> wwd (same pad) and k1d (valid)
__global__ void boxsum_kernel() {
    int idx = blockIdx.x * blockDim.x + threadIdx.x;
    if (idx < BATCH * MM) {
        int b = idx / MM, m = idx - b * MM;
        int y = m / WW, x = m - y * WW;
        float s = 0.f;
        #pragma unroll
        for (int dy = 0; dy < 3; dy++)
            #pragma unroll
            for (int dx = 0; dx < 3; dx++) {
                int yy = y + dy - 1, xx = x + dx - 1;
                if (yy >= 0 && yy < HH && xx >= 0 && xx < WW)
                    s += g_sg[(b * HH + yy) * WW + xx];
            }
        g_wwd[idx] = s;
    } else if (idx < BATCH * MM + BATCH * CC) {
        int id2 = idx - BATCH * MM;
        int b = id2 / CC, j = id2 - b * CC;
        int jy = j / HC, jx = j - jy * HC;
        float s = 0.f;
        #pragma unroll
        for (int dy = 0; dy < 3; dy++)
            #pragma unroll
            for (int dx = 0; dx < 3; dx++)
                s += g_sbg[(b * HH + jy + dy) * WW + jx + dx];
        g_k1d[id2] = s;
    }
}

// ---------------------------------------------------------------------------
// gemmE (SYRK form): G = gin @ gin^T is symmetric; E[p,q] = G[p,q]*mask[q].
// Compute only lower-triangular tiles (i >= j); write the tile coalesced, and
// for off-diagonal tiles stage the transpose through smem so the mirror write
// is ALSO row-major coalesced float4 stores (round-5's scattered mirror writes
// caused 8x write amplification).  mask in {0,1} => bit-exact.
#define NTILE (MM / 64)                       // 36
#define NPAIR (NTILE * (NTILE + 1) / 2)       // 666
__global__ __launch_bounds__(256) void gemmE_syrk_kernel(const float* __restrict__ gin,
                                                         const float* __restrict__ mask) {
    __shared__ float As[16][64];
    __shared__ float Bs[16][64];
    __shared__ float sT[64][65];              // transpose staging (mirror tile)
    int b = blockIdx.y;
    int t = blockIdx.x;
    // triangular index: t -> (i, j), j <= i
    int i = (int)((sqrtf(8.f * t + 1.f) - 1.f) * 0.5f);
    while ((i + 1) * (i + 2) / 2 <= t) i++;
    while (i * (i + 1) / 2 > t) i--;
    int j = t - i * (i + 1) / 2;
    int p0 = i * 64;
    int q0 = j * 64;

    int tid = threadIdx.x;
    int lk = (tid & 3) * 4;
    int lr = tid >> 2;
    int ty = tid >> 4, tx = tid & 15;

    const float* A = gin + (size_t)b * MM * DD;

    float acc[4][4];
    #pragma unroll
    for (int ii = 0; ii < 4; ii++)
        #pragma unroll
        for (int jj = 0; jj < 4; jj++) acc[ii][jj] = 0.f;

    #pragma unroll
    for (int k0 = 0; k0 < DD; k0 += 16) {
        float4 va = *(const float4*)(A + (p0 + lr) * DD + k0 + lk);
        As[lk + 0][lr] = va.x; As[lk + 1][lr] = va.y;
        As[lk + 2][lr] = va.z; As[lk + 3][lr] = va.w;
        float4 vb = *(const float4*)(A + (q0 + lr) * DD + k0 + lk);
        Bs[lk + 0][lr] = vb.x; Bs[lk + 1][lr] = vb.y;
        Bs[lk + 2][lr] = vb.z; Bs[lk + 3][lr] = vb.w;
        __syncthreads();
        #pragma unroll
        for (int k = 0; k < 16; k++) {
            float4 a4 = *(const float4*)(&As[k][ty * 4]);
            float4 b4 = *(const float4*)(&Bs[k][tx * 4]);
            float av[4] = {a4.x, a4.y, a4.z, a4.w};
            float bv[4] = {b4.x, b4.y, b4.z, b4.w};
            #pragma unroll
            for (int ii = 0; ii < 4; ii++)
                #pragma unroll
                for (int jj = 0; jj < 4; jj++) acc[ii][jj] += av[ii] * bv[jj];
        }
        __syncthreads();
    }

    float* Eb = g_E + (size_t)b * MM * MM;
    const float* mb = mask + b * MM;

    // normal write: E[p0+r, q0+c] = acc[r][c] * mask[q0+c]   (coalesced)
    float mq[4];
    #pragma unroll
    for (int c = 0; c < 4; c++) mq[c] = mb[q0 + tx * 4 + c];
    #pragma unroll
    for (int r = 0; r < 4; r++) {
        float4 v;
        v.x = acc[r][0] * mq[0]; v.y = acc[r][1] * mq[1];
        v.z = acc[r][2] * mq[2]; v.w = acc[r][3] * mq[3];
        *(float4*)(Eb + (size_t)(p0 + ty * 4 + r) * MM + q0 + tx * 4) = v;
    }

    if (i != j) {
        // stage mirror tile: sT[mirror_row = q-col][mirror_col = p-row] = acc * mask[p]
        float mp[4];
        #pragma unroll
        for (int r = 0; r < 4; r++) mp[r] = mb[p0 + ty * 4 + r];
        #pragma unroll
        for (int r = 0; r < 4; r++)
            #pragma unroll
            for (int c = 0; c < 4; c++)
                sT[tx * 4 + c][ty * 4 + r] = acc[r][c] * mp[r];
        __syncthreads();
        // coalesced mirror write: 1024 float4 chunks, 4 per thread
        #pragma unroll
        for (int rr = 0; rr < 4; rr++) {
            int idx = tid + 256 * rr;
            int row = idx >> 4;            // 0..63  (q-side row)
            int ch  = idx & 15;            // float4 chunk within row
            float4 v;
            v.x = sT[row][ch * 4 + 0]; v.y = sT[row][ch * 4 + 1];
            v.z = sT[row][ch * 4 + 2]; v.w = sT[row][ch * 4 + 3];
            *(float4*)(Eb + (size_t)(q0 + row) * MM + p0 + ch * 4) = v;
        }
    }
}

// ---------------------------------------------------------------------------
// Block-wide sum over 256 threads via shuffle + 8-slot smem.
__device__ __forceinline__ float block_sum256(float v, float* red) {
    int tid = threadIdx.x;
    #pragma unroll
    for (int o = 16; o > 0; o >>= 1) v += __shfl_xor_sync(0xffffffffu, v, o);
    __syncthreads();                 // protect red from previous use
    if ((tid & 31) == 0) red[tid >> 5] = v;
    __syncthreads();
    float tot = red[0] + red[1] + red[2] + red[3] + red[4] + red[5] + red[6] + red[7];
    return tot;
}

// ---------------------------------------------------------------------------
// Fused DS + tanh-normalized softmax.  One CTA per output row m.
// All 9 tap addresses = base + qb + (dy*48+dx)*(MM+1)  (compile-time tap consts).
__global__ __launch_bounds__(256) void ds_softmax_kernel() {
    __shared__ float red[8];
    int row = blockIdx.x;
    int b = row / MM, m = row - b * MM;
    int y = m / WW, x = m - y * WW;
    int tid = threadIdx.x;

    const float* Eb = g_E + (size_t)b * MM * MM;
    const float* base = Eb + (ptrdiff_t)((y - 1) * WW + (x - 1)) * MM;
    float wv = g_wwd[row];
    const float* k1 = g_k1d + b * CC;

    bool tvy[3], tvx[3];
    #pragma unroll
    for (int t = 0; t < 3; t++) {
        tvy[t] = (unsigned)(y + t - 1) < (unsigned)HH;
        tvx[t] = (unsigned)(x + t - 1) < (unsigned)WW;
    }
    bool interior = tvy[0] && tvy[2] && tvx[0] && tvx[2];

    float v[9];
    float s = 0.f;

    if (interior) {
        #pragma unroll
        for (int i = 0; i < 9; i++) {
            int n = tid + 256 * i;
            if (n < CC) {
                int jy = n / HC, jx = n - jy * HC;
                const float* p = base + (jy * WW + jx);
                float cs = 0.f;
                #pragma unroll
                for (int dy = 0; dy < 3; dy++)
                    #pragma unroll
                    for (int dx = 0; dx < 3; dx++)
                        cs += p[(dy * WW + dx) * (MM + 1)];
                float val = fmaf(-2.f, cs, k1[n] + wv);
                v[i] = val;
                s += val;
            } else v[i] = 0.f;
        }
    } else {
        #pragma unroll
        for (int i = 0; i < 9; i++) {
            int n = tid + 256 * i;
            if (n < CC) {
                int jy = n / HC, jx = n - jy * HC;
                const float* p = base + (jy * WW + jx);
                float cs = 0.f;
                #pragma unroll
                for (int dy = 0; dy < 3; dy++)
                    #pragma unroll
                    for (int dx = 0; dx < 3; dx++)
                        if (tvy[dy] && tvx[dx])
                            cs += p[(dy * WW + dx) * (MM + 1)];
                float val = fmaf(-2.f, cs, k1[n] + wv);
                v[i] = val;
                s += val;
            } else v[i] = 0.f;
        }
    }

    float mu = block_sum256(s, red) * (1.0f / CC);

    float s2 = 0.f;
    #pragma unroll
    for (int i = 0; i < 9; i++) {
        int n = tid + 256 * i;
        if (n < CC) { float d = v[i] - mu; s2 = fmaf(d, d, s2); }
    }
    float isd = rsqrtf(block_sum256(s2, red) * (1.0f / CC));

    // e = exp(-TEMP*tanh(w)) = exp(100/(e^{2w}+1) - 50),  w=(v-mu)*isd
    float se = 0.f;
    #pragma unroll
    for (int i = 0; i < 9; i++) {
        int n = tid + 256 * i;
        if (n < CC) {
            float w = (v[i] - mu) * isd;
            float u = __expf(2.f * w);
            float e = __expf(__fdividef(100.f, u + 1.f) - 50.f);
            v[i] = e;
            se += e;
        }
    }
    float inv = 1.0f / block_sum256(se, red);

    float* rp = g_DS + (size_t)row * CC;
    #pragma unroll
    for (int i = 0; i < 9; i++) {
        int n = tid + 256 * i;
        if (n < CC) rp[n] = v[i] * inv;
    }
}

// ---------------------------------------------------------------------------
// S gather: S[b,m,q] = sum_{dy,dx} CA[(y+1-dy, x+1-dx), (qy-dy)*46 + (qx-dx)]
__global__ __launch_bounds__(256) void s_gather_kernel() {
    int row = blockIdx.x;
    int b = row / MM, m = row - b * MM;
    int y = m / WW, x = m - y * WW;
    int tid = threadIdx.x;

    const float* CAb = g_DS + (size_t)b * MM * CC;
    const float* basep = CAb + (ptrdiff_t)((y + 1) * WW + (x + 1)) * CC;

    bool tvy[3], tvx[3];
    #pragma unroll
    for (int t = 0; t < 3; t++) {
        tvy[t] = (unsigned)(y + 1 - t) < (unsigned)HH;
        tvx[t] = (unsigned)(x + 1 - t) < (unsigned)WW;
    }
    bool interior_m = tvy[2] && tvx[2] && tvy[0] && tvx[0]; // y,x in [1,46]

    float* Sout = g_E + (size_t)b * MM * MM + (size_t)m * MM;

    if (interior_m) {
        for (int q = tid; q < MM; q += 256) {
            int qy = q / WW, qx = q - qy * WW;
            const float* p = basep + (qy * HC + qx);
            float s = 0.f;
            if (qy >= 2 && qy <= 45 && qx >= 2 && qx <= 45) {
                #pragma unroll
                for (int dy = 0; dy < 3; dy++)
                    #pragma unroll
                    for (int dx = 0; dx < 3; dx++)
                        s += p[-(dy * (WW * CC + HC) + dx * (CC + 1))];
            } else {
                #pragma unroll
                for (int dy = 0; dy < 3; dy++)
                    #pragma unroll
                    for (int dx = 0; dx < 3; dx++)
                        if ((unsigned)(qy - dy) < (unsigned)HC &&
                            (unsigned)(qx - dx) < (unsigned)HC)
                            s += p[-(dy * (WW * CC + HC) + dx * (CC + 1))];
            }
            Sout[q] = s;
        }
    } else {
        for (int q = tid; q < MM; q += 256) {
            int qy = q / WW, qx = q - qy * WW;
            const float* p = basep + (qy * HC + qx);
            float s = 0.f;
            #pragma unroll
            for (int dy = 0; dy < 3; dy++)
                #pragma unroll
                for (int dx = 0; dx < 3; dx++)
                    if (tvy[dy] && tvx[dx] &&
                        (unsigned)(qy - dy) < (unsigned)HC &&
                        (unsigned)(qx - dx) < (unsigned)HC)
                        s += p[-(dy * (WW * CC + HC) + dx * (CC + 1))];
            Sout[q] = s;
        }
    }
}

// ---------------------------------------------------------------------------
// gemm_acl: acl[m,d] = sum_q S[m,q] * bg[q,d]; ACL = bg + acl/9*(1-mask).
__global__ __launch_bounds__(256) void gemm_acl_kernel(const float* __restrict__ mask) {
    __shared__ float As[16][64];
    __shared__ float Bs[16][64];
    int b  = blockIdx.y;
    int m0 = blockIdx.x * 64;
    int tid = threadIdx.x;
    int lk = (tid & 3) * 4;
    int lr = tid >> 2;
    int bj = tid >> 4, bd = (tid & 15) * 4;
    int ty = tid >> 4, tx = tid & 15;

    const float* Sb  = g_E  + (size_t)b * MM * MM;
    const float* bgb = g_bg + (size_t)b * MM * DD;

    float acc[4][4];
    #pragma unroll
    for (int i = 0; i < 4; i++)
        #pragma unroll
        for (int j = 0; j < 4; j++) acc[i][j] = 0.f;

    for (int k0 = 0; k0 < MM; k0 += 16) {
        float4 va = *(const float4*)(Sb + (size_t)(m0 + lr) * MM + k0 + lk);
        As[lk + 0][lr] = va.x; As[lk + 1][lr] = va.y;
        As[lk + 2][lr] = va.z; As[lk + 3][lr] = va.w;
        float4 vb = *(const float4*)(bgb + (k0 + bj) * DD + bd);
        *(float4*)(&Bs[bj][bd]) = vb;
        __syncthreads();
        #pragma unroll
        for (int k = 0; k < 16; k++) {
            float4 a4 = *(const float4*)(&As[k][ty * 4]);
            float4 b4 = *(const float4*)(&Bs[k][tx * 4]);
            float av[4] = {a4.x, a4.y, a4.z, a4.w};
            float bv[4] = {b4.x, b4.y, b4.z, b4.w};
            #pragma unroll
            for (int i = 0; i < 4; i++)
                #pragma unroll
                for (int j = 0; j < 4; j++) acc[i][j] += av[i] * bv[j];
        }
        __syncthreads();
    }

    #pragma unroll
    for (int i = 0; i < 4; i++) {
        int rowm = b * MM + m0 + ty * 4 + i;
        float om = (1.f - mask[rowm]) * (1.f / 9.f);
        #pragma unroll
        for (int j = 0; j < 4; j++) {
            int idx = rowm * DD + tx * 4 + j;
            g_ACL[idx] = g_bg[idx] + acc[i][j] * om;
        }
    }
}

// ---------------------------------------------------------------------------
// Final: out = elu(concat(g_in, ACL) @ W2 + b2).  4 rows x 64 cols per block.
__global__ __launch_bounds__(256) void final_kernel(const float* __restrict__ gin,
                                                    const float* __restrict__ W2,
                                                    const float* __restrict__ b2,
                                                    float* __restrict__ out) {
    __shared__ float sA[4][128];
    int r0 = blockIdx.x * 4;
    int tid = threadIdx.x;
    for (int idx = tid; idx < 512; idx += 256) {
        int r = idx >> 7, k = idx & 127;
        int row = r0 + r;
        sA[r][k] = (k < DD) ? gin[row * DD + k] : g_ACL[row * DD + (k - DD)];
    }
    __syncthreads();
    int r = tid >> 6, d = tid & 63;
    int row = r0 + r;
    float acc = b2[d];
    #pragma unroll 8
    for (int k = 0; k < 128; k++) acc += sA[r][k] * W2[k * DD + d];
    out[row * DD + d] = (acc > 0.f) ? acc : expm1f(acc);
}

// ---------------------------------------------------------------------------
extern "C" void kernel_launch(void* const* d_in, const int* in_sizes, int n_in,
                              void* d_out, int out_size) {
    const float* gin  = (const float*)d_in[0];
    const float* mask = (const float*)d_in[1];
    const float* W2   = (const float*)d_in[2];
    const float* b2   = (const float*)d_in[3];
    float* out = (float*)d_out;

    prep_kernel<<<BATCH * MM, DD>>>(gin, mask);
    int tot = BATCH * MM + BATCH * CC;
    boxsum_kernel<<<(tot + 255) / 256, 256>>>();
    gemmE_syrk_kernel<<<dim3(NPAIR, BATCH), 256>>>(gin, mask);
    ds_softmax_kernel<<<BATCH * MM, 256>>>();
    s_gather_kernel<<<BATCH * MM, 256>>>();
    gemm_acl_kernel<<<dim3(MM / 64, BATCH), 256>>>(mask);
    final_kernel<<<BATCH * MM / 4, 256>>>(gin, W2, b2, out);
}

// round 7
// speedup vs baseline: 1.6933x; 1.2115x over previous
#include <cuda_runtime.h>
#include <math.h>
#include <stddef.h>

// Problem constants
#define BATCH 4
#define HH 48
#define WW 48
#define DD 64
#define HC 46                 // valid patch grid
#define CC 2116               // HC*HC candidate patches
#define MM 2304               // HH*WW locations
#define TEMPR 50.0f

// Scratch (device globals -- no runtime allocation allowed)
static __device__ float g_E [(size_t)BATCH * MM * MM];   // E Gram, then S (85 MB)
static __device__ float g_DS[(size_t)BATCH * MM * CC];   // CA (78 MB)
static __device__ float g_bg [BATCH * MM * DD];          // g_in * mask
static __device__ float g_sg [BATCH * MM];               // per-pixel sum g^2
static __device__ float g_sbg[BATCH * MM];               // per-pixel sum bg^2
static __device__ float g_wwd[BATCH * MM];               // 3x3 box sum (same pad) of g_sg
static __device__ float g_k1d[BATCH * CC];               // 3x3 box sum (valid) of g_sbg
static __device__ float g_ACL[BATCH * MM * DD];

// ---------------------------------------------------------------------------
// Kernel 0a: bg = g_in * mask ; per-pixel sums of squares
__global__ void prep_kernel(const float* __restrict__ gin, const float* __restrict__ mask) {
    int p = blockIdx.x;
    int d = threadIdx.x;
    float mv = mask[p];
    float g  = gin[p * DD + d];
    float bgv = g * mv;
    g_bg[p * DD + d] = bgv;
    __shared__ float s1[DD];
    __shared__ float s2[DD];
    s1[d] = g * g;
    s2[d] = bgv * bgv;
    __syncthreads();
    #pragma unroll
    for (int s = 32; s > 0; s >>= 1) {
        if (d < s) { s1[d] += s1[d + s]; s2[d] += s2[d + s]; }
        __syncthreads();
    }
    if (d == 0) { g_sg[p] = s1[0]; g_sbg[p] = s2[0]; }
}

// Kernel 0b: box sums -> wwd (same pad) and k1d (valid)
__global__ void boxsum_kernel() {
    int idx = blockIdx.x * blockDim.x + threadIdx.x;
    if (idx < BATCH * MM) {
        int b = idx / MM, m = idx - b * MM;
        int y = m / WW, x = m - y * WW;
        float s = 0.f;
        #pragma unroll
        for (int dy = 0; dy < 3; dy++)
            #pragma unroll
            for (int dx = 0; dx < 3; dx++) {
                int yy = y + dy - 1, xx = x + dx - 1;
                if (yy >= 0 && yy < HH && xx >= 0 && xx < WW)
                    s += g_sg[(b * HH + yy) * WW + xx];
            }
        g_wwd[idx] = s;
    } else if (idx < BATCH * MM + BATCH * CC) {
        int id2 = idx - BATCH * MM;
        int b = id2 / CC, j = id2 - b * CC;
        int jy = j / HC, jx = j - jy * HC;
        float s = 0.f;
        #pragma unroll
        for (int dy = 0; dy < 3; dy++)
            #pragma unroll
            for (int dx = 0; dx < 3; dx++)
                s += g_sbg[(b * HH + jy + dy) * WW + jx + dx];
        g_k1d[id2] = s;
    }
}

// ---------------------------------------------------------------------------
// gemmE (SYRK form): G = gin @ gin^T is symmetric; E[p,q] = G[p,q]*mask[q].
// Lower-triangular tiles only; mirror tile staged through smem for coalesced
// writes.  mask in {0,1} => bit-exact.
#define NTILE (MM / 64)                       // 36
#define NPAIR (NTILE * (NTILE + 1) / 2)       // 666
__global__ __launch_bounds__(256) void gemmE_syrk_kernel(const float* __restrict__ gin,
                                                         const float* __restrict__ mask) {
    __shared__ float As[16][64];
    __shared__ float Bs[16][64];
    __shared__ float sT[64][65];              // transpose staging (mirror tile)
    int b = blockIdx.y;
    int t = blockIdx.x;
    // triangular index: t -> (i, j), j <= i
    int i = (int)((sqrtf(8.f * t + 1.f) - 1.f) * 0.5f);
    while ((i + 1) * (i + 2) / 2 <= t) i++;
    while (i * (i + 1) / 2 > t) i--;
    int j = t - i * (i + 1) / 2;
    int p0 = i * 64;
    int q0 = j * 64;

    int tid = threadIdx.x;
    int lk = (tid & 3) * 4;
    int lr = tid >> 2;
    int ty = tid >> 4, tx = tid & 15;

    const float* A = gin + (size_t)b * MM * DD;

    float acc[4][4];
    #pragma unroll
    for (int ii = 0; ii < 4; ii++)
        #pragma unroll
        for (int jj = 0; jj < 4; jj++) acc[ii][jj] = 0.f;

    #pragma unroll
    for (int k0 = 0; k0 < DD; k0 += 16) {
        float4 va = *(const float4*)(A + (p0 + lr) * DD + k0 + lk);
        As[lk + 0][lr] = va.x; As[lk + 1][lr] = va.y;
        As[lk + 2][lr] = va.z; As[lk + 3][lr] = va.w;
        float4 vb = *(const float4*)(A + (q0 + lr) * DD + k0 + lk);
        Bs[lk + 0][lr] = vb.x; Bs[lk + 1][lr] = vb.y;
        Bs[lk + 2][lr] = vb.z; Bs[lk + 3][lr] = vb.w;
        __syncthreads();
        #pragma unroll
        for (int k = 0; k < 16; k++) {
            float4 a4 = *(const float4*)(&As[k][ty * 4]);
            float4 b4 = *(const float4*)(&Bs[k][tx * 4]);
            float av[4] = {a4.x, a4.y, a4.z, a4.w};
            float bv[4] = {b4.x, b4.y, b4.z, b4.w};
            #pragma unroll
            for (int ii = 0; ii < 4; ii++)
                #pragma unroll
                for (int jj = 0; jj < 4; jj++) acc[ii][jj] += av[ii] * bv[jj];
        }
        __syncthreads();
    }

    float* Eb = g_E + (size_t)b * MM * MM;
    const float* mb = mask + b * MM;

    // normal write: E[p0+r, q0+c] = acc[r][c] * mask[q0+c]   (coalesced)
    float mq[4];
    #pragma unroll
    for (int c = 0; c < 4; c++) mq[c] = mb[q0 + tx * 4 + c];
    #pragma unroll
    for (int r = 0; r < 4; r++) {
        float4 v;
        v.x = acc[r][0] * mq[0]; v.y = acc[r][1] * mq[1];
        v.z = acc[r][2] * mq[2]; v.w = acc[r][3] * mq[3];
        *(float4*)(Eb + (size_t)(p0 + ty * 4 + r) * MM + q0 + tx * 4) = v;
    }

    if (i != j) {
        float mp[4];
        #pragma unroll
        for (int r = 0; r < 4; r++) mp[r] = mb[p0 + ty * 4 + r];
        #pragma unroll
        for (int r = 0; r < 4; r++)
            #pragma unroll
            for (int c = 0; c < 4; c++)
                sT[tx * 4 + c][ty * 4 + r] = acc[r][c] * mp[r];
        __syncthreads();
        #pragma unroll
        for (int rr = 0; rr < 4; rr++) {
            int idx = tid + 256 * rr;
            int row = idx >> 4;
            int ch  = idx & 15;
            float4 v;
            v.x = sT[row][ch * 4 + 0]; v.y = sT[row][ch * 4 + 1];
            v.z = sT[row][ch * 4 + 2]; v.w = sT[row][ch * 4 + 3];
            *(float4*)(Eb + (size_t)(q0 + row) * MM + p0 + ch * 4) = v;
        }
    }
}

// ---------------------------------------------------------------------------
// Block-wide sum over 256 threads via shuffle + 8-slot smem.
__device__ __forceinline__ float block_sum256(float v, float* red) {
    int tid = threadIdx.x;
    #pragma unroll
    for (int o = 16; o > 0; o >>= 1) v += __shfl_xor_sync(0xffffffffu, v, o);
    __syncthreads();
    if ((tid & 31) == 0) red[tid >> 5] = v;
    __syncthreads();
    float tot = red[0] + red[1] + red[2] + red[3] + red[4] + red[5] + red[6] + red[7];
    return tot;
}

// ---------------------------------------------------------------------------
// Fused DS + tanh-normalized softmax.  One CTA per output row m.
__global__ __launch_bounds__(256) void ds_softmax_kernel() {
    __shared__ float red[8];
    int row = blockIdx.x;
    int b = row / MM, m = row - b * MM;
    int y = m / WW, x = m - y * WW;
    int tid = threadIdx.x;

    const float* Eb = g_E + (size_t)b * MM * MM;
    const float* base = Eb + (ptrdiff_t)((y - 1) * WW + (x - 1)) * MM;
    float wv = g_wwd[row];
    const float* k1 = g_k1d + b * CC;

    bool tvy[3], tvx[3];
    #pragma unroll
    for (int t = 0; t < 3; t++) {
        tvy[t] = (unsigned)(y + t - 1) < (unsigned)HH;
        tvx[t] = (unsigned)(x + t - 1) < (unsigned)WW;
    }
    bool interior = tvy[0] && tvy[2] && tvx[0] && tvx[2];

    float v[9];
    float s = 0.f;

    if (interior) {
        #pragma unroll
        for (int i = 0; i < 9; i++) {
            int n = tid + 256 * i;
            if (n < CC) {
                int jy = n / HC, jx = n - jy * HC;
                const float* p = base + (jy * WW + jx);
                float cs = 0.f;
                #pragma unroll
                for (int dy = 0; dy < 3; dy++)
                    #pragma unroll
                    for (int dx = 0; dx < 3; dx++)
                        cs += p[(dy * WW + dx) * (MM + 1)];
                float val = fmaf(-2.f, cs, k1[n] + wv);
                v[i] = val;
                s += val;
            } else v[i] = 0.f;
        }
    } else {
        #pragma unroll
        for (int i = 0; i < 9; i++) {
            int n = tid + 256 * i;
            if (n < CC) {
                int jy = n / HC, jx = n - jy * HC;
                const float* p = base + (jy * WW + jx);
                float cs = 0.f;
                #pragma unroll
                for (int dy = 0; dy < 3; dy++)
                    #pragma unroll
                    for (int dx = 0; dx < 3; dx++)
                        if (tvy[dy] && tvx[dx])
                            cs += p[(dy * WW + dx) * (MM + 1)];
                float val = fmaf(-2.f, cs, k1[n] + wv);
                v[i] = val;
                s += val;
            } else v[i] = 0.f;
        }
    }

    float mu = block_sum256(s, red) * (1.0f / CC);

    float s2 = 0.f;
    #pragma unroll
    for (int i = 0; i < 9; i++) {
        int n = tid + 256 * i;
        if (n < CC) { float d = v[i] - mu; s2 = fmaf(d, d, s2); }
    }
    float isd = rsqrtf(block_sum256(s2, red) * (1.0f / CC));

    float se = 0.f;
    #pragma unroll
    for (int i = 0; i < 9; i++) {
        int n = tid + 256 * i;
        if (n < CC) {
            float w = (v[i] - mu) * isd;
            float u = __expf(2.f * w);
            float e = __expf(__fdividef(100.f, u + 1.f) - 50.f);
            v[i] = e;
            se += e;
        }
    }
    float inv = 1.0f / block_sum256(se, red);

    float* rp = g_DS + (size_t)row * CC;
    #pragma unroll
    for (int i = 0; i < 9; i++) {
        int n = tid + 256 * i;
        if (n < CC) rp[n] = v[i] * inv;
    }
}

// ---------------------------------------------------------------------------
// S gather: S[b,m,q] = sum_{dy,dx} CA[(y+1-dy, x+1-dx), (qy-dy)*46 + (qx-dx)]
__global__ __launch_bounds__(256) void s_gather_kernel() {
    int row = blockIdx.x;
    int b = row / MM, m = row - b * MM;
    int y = m / WW, x = m - y * WW;
    int tid = threadIdx.x;

    const float* CAb = g_DS + (size_t)b * MM * CC;
    const float* basep = CAb + (ptrdiff_t)((y + 1) * WW + (x + 1)) * CC;

    bool tvy[3], tvx[3];
    #pragma unroll
    for (int t = 0; t < 3; t++) {
        tvy[t] = (unsigned)(y + 1 - t) < (unsigned)HH;
        tvx[t] = (unsigned)(x + 1 - t) < (unsigned)WW;
    }
    bool interior_m = tvy[2] && tvx[2] && tvy[0] && tvx[0];

    float* Sout = g_E + (size_t)b * MM * MM + (size_t)m * MM;

    if (interior_m) {
        for (int q = tid; q < MM; q += 256) {
            int qy = q / WW, qx = q - qy * WW;
            const float* p = basep + (qy * HC + qx);
            float s = 0.f;
            if (qy >= 2 && qy <= 45 && qx >= 2 && qx <= 45) {
                #pragma unroll
                for (int dy = 0; dy < 3; dy++)
                    #pragma unroll
                    for (int dx = 0; dx < 3; dx++)
                        s += p[-(dy * (WW * CC + HC) + dx * (CC + 1))];
            } else {
                #pragma unroll
                for (int dy = 0; dy < 3; dy++)
                    #pragma unroll
                    for (int dx = 0; dx < 3; dx++)
                        if ((unsigned)(qy - dy) < (unsigned)HC &&
                            (unsigned)(qx - dx) < (unsigned)HC)
                            s += p[-(dy * (WW * CC + HC) + dx * (CC + 1))];
            }
            Sout[q] = s;
        }
    } else {
        for (int q = tid; q < MM; q += 256) {
            int qy = q / WW, qx = q - qy * WW;
            const float* p = basep + (qy * HC + qx);
            float s = 0.f;
            #pragma unroll
            for (int dy = 0; dy < 3; dy++)
                #pragma unroll
                for (int dx = 0; dx < 3; dx++)
                    if (tvy[dy] && tvx[dx] &&
                        (unsigned)(qy - dy) < (unsigned)HC &&
                        (unsigned)(qx - dx) < (unsigned)HC)
                        s += p[-(dy * (WW * CC + HC) + dx * (CC + 1))];
            Sout[q] = s;
        }
    }
}

// ---------------------------------------------------------------------------
// gemm_acl: acl[m,d] = sum_q S[m,q] * bg[q,d]; ACL = bg + acl/9*(1-mask).
// BM=64, BN=32, BK=16, 128 threads, 4x4 micro, double-buffered smem with
// register prefetch (grid 288 = 2 CTA/SM; 1 sync per k-tile).
#define NKT (MM / 16)   // 144 k-tiles
__global__ __launch_bounds__(128) void gemm_acl_kernel(const float* __restrict__ mask) {
    __shared__ float As[2][16][68];   // As[buf][k][m], pad 68 (16B-aligned rows)
    __shared__ float Bs[2][16][32];
    int b  = blockIdx.z;
    int m0 = blockIdx.x * 64;
    int n0 = blockIdx.y * 32;
    int tid = threadIdx.x;
    int ty = tid >> 3, tx = tid & 7;      // compute map: rows ty*4, cols tx*4

    // A loader: idx in {tid, tid+128}: r = idx>>2 (0..63), kc = idx&3
    int ar0 = tid >> 2,        akc0 = (tid & 3) * 4;
    int ar1 = (tid + 128) >> 2, akc1 = (tid & 3) * 4;   // idx+128 -> r+32, same kc
    // B loader: kr = tid>>3 (0..15), cc = tid&7
    int bkr = tid >> 3, bcc = (tid & 7) * 4;

    const float* Sb  = g_E  + (size_t)b * MM * MM + (size_t)m0 * MM;
    const float* bgb = g_bg + (size_t)b * MM * DD;

    float4 pa0, pa1, pb;
    // prefetch tile 0
    pa0 = *(const float4*)(Sb + (size_t)ar0 * MM + akc0);
    pa1 = *(const float4*)(Sb + (size_t)ar1 * MM + akc1);
    pb  = *(const float4*)(bgb + bkr * DD + n0 + bcc);
    // store tile 0 -> buf 0
    As[0][akc0 + 0][ar0] = pa0.x; As[0][akc0 + 1][ar0] = pa0.y;
    As[0][akc0 + 2][ar0] = pa0.z; As[0][akc0 + 3][ar0] = pa0.w;
    As[0][akc1 + 0][ar1] = pa1.x; As[0][akc1 + 1][ar1] = pa1.y;
    As[0][akc1 + 2][ar1] = pa1.z; As[0][akc1 + 3][ar1] = pa1.w;
    *(float4*)(&Bs[0][bkr][bcc]) = pb;
    __syncthreads();

    float acc[4][4];
    #pragma unroll
    for (int i = 0; i < 4; i++)
        #pragma unroll
        for (int j = 0; j < 4; j++) acc[i][j] = 0.f;

    for (int t = 0; t < NKT; t++) {
        int cur = t & 1;
        if (t + 1 < NKT) {
            int k0 = (t + 1) * 16;
            pa0 = *(const float4*)(Sb + (size_t)ar0 * MM + k0 + akc0);
            pa1 = *(const float4*)(Sb + (size_t)ar1 * MM + k0 + akc1);
            pb  = *(const float4*)(bgb + (k0 + bkr) * DD + n0 + bcc);
        }
        #pragma unroll
        for (int k = 0; k < 16; k++) {
            float4 a4 = *(const float4*)(&As[cur][k][ty * 4]);
            float4 b4 = *(const float4*)(&Bs[cur][k][tx * 4]);
            float av[4] = {a4.x, a4.y, a4.z, a4.w};
            float bv[4] = {b4.x, b4.y, b4.z, b4.w};
            #pragma unroll
            for (int i = 0; i < 4; i++)
                #pragma unroll
                for (int j = 0; j < 4; j++) acc[i][j] += av[i] * bv[j];
        }
        if (t + 1 < NKT) {
            int nxt = 1 - cur;
            As[nxt][akc0 + 0][ar0] = pa0.x; As[nxt][akc0 + 1][ar0] = pa0.y;
            As[nxt][akc0 + 2][ar0] = pa0.z; As[nxt][akc0 + 3][ar0] = pa0.w;
            As[nxt][akc1 + 0][ar1] = pa1.x; As[nxt][akc1 + 1][ar1] = pa1.y;
            As[nxt][akc1 + 2][ar1] = pa1.z; As[nxt][akc1 + 3][ar1] = pa1.w;
            *(float4*)(&Bs[nxt][bkr][bcc]) = pb;
        }
        __syncthreads();
    }

    #pragma unroll
    for (int i = 0; i < 4; i++) {
        int rowm = b * MM + m0 + ty * 4 + i;
        float om = (1.f - mask[rowm]) * (1.f / 9.f);
        float4 v;
        int idx = rowm * DD + n0 + tx * 4;
        v.x = g_bg[idx + 0] + acc[i][0] * om;
        v.y = g_bg[idx + 1] + acc[i][1] * om;
        v.z = g_bg[idx + 2] + acc[i][2] * om;
        v.w = g_bg[idx + 3] + acc[i][3] * om;
        *(float4*)(&g_ACL[idx]) = v;
    }
}

// ---------------------------------------------------------------------------
// Final: out = elu(concat(g_in, ACL) @ W2 + b2).  4 rows x 64 cols per block.
__global__ __launch_bounds__(256) void final_kernel(const float* __restrict__ gin,
                                                    const float* __restrict__ W2,
                                                    const float* __restrict__ b2,
                                                    float* __restrict__ out) {
    __shared__ float sA[4][128];
    int r0 = blockIdx.x * 4;
    int tid = threadIdx.x;
    for (int idx = tid; idx < 512; idx += 256) {
        int r = idx >> 7, k = idx & 127;
        int row = r0 + r;
        sA[r][k] = (k < DD) ? gin[row * DD + k] : g_ACL[row * DD + (k - DD)];
    }
    __syncthreads();
    int r = tid >> 6, d = tid & 63;
    int row = r0 + r;
    float acc = b2[d];
    #pragma unroll 8
    for (int k = 0; k < 128; k++) acc += sA[r][k] * W2[k * DD + d];
    out[row * DD + d] = (acc > 0.f) ? acc : expm1f(acc);
}

// ---------------------------------------------------------------------------
extern "C" void kernel_launch(void* const* d_in, const int* in_sizes, int n_in,
                              void* d_out, int out_size) {
    const float* gin  = (const float*)d_in[0];
    const float* mask = (const float*)d_in[1];
    const float* W2   = (const float*)d_in[2];
    const float* b2   = (const float*)d_in[3];
    float* out = (float*)d_out;

    prep_kernel<<<BATCH * MM, DD>>>(gin, mask);
    int tot = BATCH * MM + BATCH * CC;
    boxsum_kernel<<<(tot + 255) / 256, 256>>>();
    gemmE_syrk_kernel<<<dim3(NPAIR, BATCH), 256>>>(gin, mask);
    ds_softmax_kernel<<<BATCH * MM, 256>>>();
    s_gather_kernel<<<BATCH * MM, 256>>>();
    gemm_acl_kernel<<<dim3(MM / 64, DD / 32, BATCH), 128>>>(mask);
    final_kernel<<<BATCH * MM / 4, 256>>>(gin, W2, b2, out);
}

// round 13
// speedup vs baseline: 1.7692x; 1.0448x over previous
#include <cuda_runtime.h>
#include <math.h>
#include <stddef.h>

// Problem constants
#define BATCH 4
#define HH 48
#define WW 48
#define DD 64
#define HC 46                 // valid patch grid
#define CC 2116               // HC*HC candidate patches
#define MM 2304               // HH*WW locations
#define TEMPR 50.0f

// Scratch (device globals -- no runtime allocation allowed)
static __device__ float g_E [(size_t)BATCH * MM * MM];   // E Gram, then S (85 MB)
static __device__ float g_DS[(size_t)BATCH * MM * CC];   // CA (78 MB)
static __device__ float g_bg [BATCH * MM * DD];          // g_in * mask
static __device__ float g_sg [BATCH * MM];               // per-pixel sum g^2
static __device__ float g_sbg[BATCH * MM];               // per-pixel sum bg^2
static __device__ float g_wwd[BATCH * MM];               // 3x3 box sum (same pad) of g_sg
static __device__ float g_k1d[BATCH * CC];               // 3x3 box sum (valid) of g_sbg
static __device__ float g_ACL[BATCH * MM * DD];

// ---------------------------------------------------------------------------
// Kernel 0a: bg = g_in * mask ; per-pixel sums of squares
__global__ void prep_kernel(const float* __restrict__ gin, const float* __restrict__ mask) {
    int p = blockIdx.x;
    int d = threadIdx.x;
    float mv = mask[p];
    float g  = gin[p * DD + d];
    float bgv = g * mv;
    g_bg[p * DD + d] = bgv;
    __shared__ float s1[DD];
    __shared__ float s2[DD];
    s1[d] = g * g;
    s2[d] = bgv * bgv;
    __syncthreads();
    #pragma unroll
    for (int s = 32; s > 0; s >>= 1) {
        if (d < s) { s1[d] += s1[d + s]; s2[d] += s2[d + s]; }
        __syncthreads();
    }
    if (d == 0) { g_sg[p] = s1[0]; g_sbg[p] = s2[0]; }
}

// Kernel 0b: box sums -> wwd (same pad) and k1d (valid)
__global__ void boxsum_kernel() {
    int idx = blockIdx.x * blockDim.x + threadIdx.x;
    if (idx < BATCH * MM) {
        int b = idx / MM, m = idx - b * MM;
        int y = m / WW, x = m - y * WW;
        float s = 0.f;
        #pragma unroll
        for (int dy = 0; dy < 3; dy++)
            #pragma unroll
            for (int dx = 0; dx < 3; dx++) {
                int yy = y + dy - 1, xx = x + dx - 1;
                if (yy >= 0 && yy < HH && xx >= 0 && xx < WW)
                    s += g_sg[(b * HH + yy) * WW + xx];
            }
        g_wwd[idx] = s;
    } else if (idx < BATCH * MM + BATCH * CC) {
        int id2 = idx - BATCH * MM;
        int b = id2 / CC, j = id2 - b * CC;
        int jy = j / HC, jx = j - jy * HC;
        float s = 0.f;
        #pragma unroll
        for (int dy = 0; dy < 3; dy++)
            #pragma unroll
            for (int dx = 0; dx < 3; dx++)
                s += g_sbg[(b * HH + jy + dy) * WW + jx + dx];
        g_k1d[id2] = s;
    }
}

// ---------------------------------------------------------------------------
// gemmE (SYRK): G = gin @ gin^T symmetric; E[p,q] = G[p,q]*mask[q].
// K=64 staged into smem in ONE shot -> single sync, no k-tiling round-trips.
// Mirror tile staged through smem (overlaid on As/Bs) for coalesced writes.
#define NTILE (MM / 64)                       // 36
#define NPAIR (NTILE * (NTILE + 1) / 2)       // 666
__global__ __launch_bounds__(256) void gemmE_syrk_kernel(const float* __restrict__ gin,
                                                         const float* __restrict__ mask) {
    __shared__ float buf[2 * 64 * 64];        // 32 KB: As | Bs, later overlaid by sT
    float (*As)[64] = (float(*)[64])buf;
    float (*Bs)[64] = (float(*)[64])(buf + 64 * 64);

    int b = blockIdx.y;
    int t = blockIdx.x;
    // triangular index: t -> (i, j), j <= i
    int i = (int)((sqrtf(8.f * t + 1.f) - 1.f) * 0.5f);
    while ((i + 1) * (i + 2) / 2 <= t) i++;
    while (i * (i + 1) / 2 > t) i--;
    int j = t - i * (i + 1) / 2;
    int p0 = i * 64;
    int q0 = j * 64;

    int tid = threadIdx.x;
    int lk = (tid & 3) * 4;
    int lr = tid >> 2;
    int ty = tid >> 4, tx = tid & 15;

    const float* A = gin + (size_t)b * MM * DD;

    // load ALL of K=64 for both tiles (8 LDG.128 in flight), one sync
    #pragma unroll
    for (int k0 = 0; k0 < DD; k0 += 16) {
        float4 va = *(const float4*)(A + (p0 + lr) * DD + k0 + lk);
        As[k0 + lk + 0][lr] = va.x; As[k0 + lk + 1][lr] = va.y;
        As[k0 + lk + 2][lr] = va.z; As[k0 + lk + 3][lr] = va.w;
        float4 vb = *(const float4*)(A + (q0 + lr) * DD + k0 + lk);
        Bs[k0 + lk + 0][lr] = vb.x; Bs[k0 + lk + 1][lr] = vb.y;
        Bs[k0 + lk + 2][lr] = vb.z; Bs[k0 + lk + 3][lr] = vb.w;
    }
    __syncthreads();

    float acc[4][4];
    #pragma unroll
    for (int ii = 0; ii < 4; ii++)
        #pragma unroll
        for (int jj = 0; jj < 4; jj++) acc[ii][jj] = 0.f;

    #pragma unroll 8
    for (int k = 0; k < DD; k++) {
        float4 a4 = *(const float4*)(&As[k][ty * 4]);
        float4 b4 = *(const float4*)(&Bs[k][tx * 4]);
        float av[4] = {a4.x, a4.y, a4.z, a4.w};
        float bv[4] = {b4.x, b4.y, b4.z, b4.w};
        #pragma unroll
        for (int ii = 0; ii < 4; ii++)
            #pragma unroll
            for (int jj = 0; jj < 4; jj++) acc[ii][jj] += av[ii] * bv[jj];
    }

    float* Eb = g_E + (size_t)b * MM * MM;
    const float* mb = mask + b * MM;

    // normal write: E[p0+r, q0+c] = acc[r][c] * mask[q0+c]   (coalesced)
    float mq[4];
    #pragma unroll
    for (int c = 0; c < 4; c++) mq[c] = mb[q0 + tx * 4 + c];
    #pragma unroll
    for (int r = 0; r < 4; r++) {
        float4 v;
        v.x = acc[r][0] * mq[0]; v.y = acc[r][1] * mq[1];
        v.z = acc[r][2] * mq[2]; v.w = acc[r][3] * mq[3];
        *(float4*)(Eb + (size_t)(p0 + ty * 4 + r) * MM + q0 + tx * 4) = v;
    }

    if (i != j) {
        // overlay transpose staging on As/Bs (dead after compute)
        float (*sT)[65] = (float(*)[65])buf;
        float mp[4];
        #pragma unroll
        for (int r = 0; r < 4; r++) mp[r] = mb[p0 + ty * 4 + r];
        __syncthreads();   // everyone done reading As/Bs before overlay writes
        #pragma unroll
        for (int r = 0; r < 4; r++)
            #pragma unroll
            for (int c = 0; c < 4; c++)
                sT[tx * 4 + c][ty * 4 + r] = acc[r][c] * mp[r];
        __syncthreads();
        #pragma unroll
        for (int rr = 0; rr < 4; rr++) {
            int idx = tid + 256 * rr;
            int row = idx >> 4;
            int ch  = idx & 15;
            float4 v;
            v.x = sT[row][ch * 4 + 0]; v.y = sT[row][ch * 4 + 1];
            v.z = sT[row][ch * 4 + 2]; v.w = sT[row][ch * 4 + 3];
            *(float4*)(Eb + (size_t)(q0 + row) * MM + p0 + ch * 4) = v;
        }
    }
}

// ---------------------------------------------------------------------------
// Block-wide sum over 256 threads via shuffle + 8-slot smem.
__device__ __forceinline__ float block_sum256(float v, float* red) {
    int tid = threadIdx.x;
    #pragma unroll
    for (int o = 16; o > 0; o >>= 1) v += __shfl_xor_sync(0xffffffffu, v, o);
    __syncthreads();
    if ((tid & 31) == 0) red[tid >> 5] = v;
    __syncthreads();
    float tot = red[0] + red[1] + red[2] + red[3] + red[4] + red[5] + red[6] + red[7];
    return tot;
}

// ---------------------------------------------------------------------------
// Fused DS + tanh-normalized softmax.  One CTA per output row m.
__global__ __launch_bounds__(256) void ds_softmax_kernel() {
    __shared__ float red[8];
    int row = blockIdx.x;
    int b = row / MM, m = row - b * MM;
    int y = m / WW, x = m - y * WW;
    int tid = threadIdx.x;

    const float* Eb = g_E + (size_t)b * MM * MM;
    const float* base = Eb + (ptrdiff_t)((y - 1) * WW + (x - 1)) * MM;
    float wv = g_wwd[row];
    const float* k1 = g_k1d + b * CC;

    bool tvy[3], tvx[3];
    #pragma unroll
    for (int t = 0; t < 3; t++) {
        tvy[t] = (unsigned)(y + t - 1) < (unsigned)HH;
        tvx[t] = (unsigned)(x + t - 1) < (unsigned)WW;
    }
    bool interior = tvy[0] && tvy[2] && tvx[0] && tvx[2];

    float v[9];
    float s = 0.f;

    if (interior) {
        #pragma unroll
        for (int i = 0; i < 9; i++) {
            int n = tid + 256 * i;
            if (n < CC) {
                int jy = n / HC, jx = n - jy * HC;
                const float* p = base + (jy * WW + jx);
                float cs = 0.f;
                #pragma unroll
                for (int dy = 0; dy < 3; dy++)
                    #pragma unroll
                    for (int dx = 0; dx < 3; dx++)
                        cs += p[(dy * WW + dx) * (MM + 1)];
                float val = fmaf(-2.f, cs, k1[n] + wv);
                v[i] = val;
                s += val;
            } else v[i] = 0.f;
        }
    } else {
        #pragma unroll
        for (int i = 0; i < 9; i++) {
            int n = tid + 256 * i;
            if (n < CC) {
                int jy = n / HC, jx = n - jy * HC;
                const float* p = base + (jy * WW + jx);
                float cs = 0.f;
                #pragma unroll
                for (int dy = 0; dy < 3; dy++)
                    #pragma unroll
                    for (int dx = 0; dx < 3; dx++)
                        if (tvy[dy] && tvx[dx])
                            cs += p[(dy * WW + dx) * (MM + 1)];
                float val = fmaf(-2.f, cs, k1[n] + wv);
                v[i] = val;
                s += val;
            } else v[i] = 0.f;
        }
    }

    float mu = block_sum256(s, red) * (1.0f / CC);

    float s2 = 0.f;
    #pragma unroll
    for (int i = 0; i < 9; i++) {
        int n = tid + 256 * i;
        if (n < CC) { float d = v[i] - mu; s2 = fmaf(d, d, s2); }
    }
    float isd = rsqrtf(block_sum256(s2, red) * (1.0f / CC));

    float se = 0.f;
    #pragma unroll
    for (int i = 0; i < 9; i++) {
        int n = tid + 256 * i;
        if (n < CC) {
            float w = (v[i] - mu) * isd;
            float u = __expf(2.f * w);
            float e = __expf(__fdividef(100.f, u + 1.f) - 50.f);
            v[i] = e;
            se += e;
        }
    }
    float inv = 1.0f / block_sum256(se, red);

    float* rp = g_DS + (size_t)row * CC;
    #pragma unroll
    for (int i = 0; i < 9; i++) {
        int n = tid + 256 * i;
        if (n < CC) rp[n] = v[i] * inv;
    }
}

// ---------------------------------------------------------------------------
// S gather, PAIRED rows (y, y+1) per CTA: 6 of 9 taps of the second row hit
// CA rows just streamed for the first row -> L1 reuse cuts L2 traffic ~1/3.
// S[b,m,q] = sum_{dy,dx} CA[(y+1-dy, x+1-dx), (qy-dy)*46 + (qx-dx)]
__global__ __launch_bounds__(256) void s_gather_kernel() {
    int pid = blockIdx.x;
    int b = pid / (MM / 2);
    int mp = pid - b * (MM / 2);
    int yh = mp / WW, x = mp - yh * WW;
    int y0 = yh * 2;                       // rows y0 and y0+1, same x
    int tid = threadIdx.x;

    const float* CAb = g_DS + (size_t)b * MM * CC;
    const float* base0 = CAb + (ptrdiff_t)((y0 + 1) * WW + (x + 1)) * CC;
    const float* base1 = base0 + (ptrdiff_t)WW * CC;

    unsigned pm0 = 0, pm1 = 0;
    #pragma unroll
    for (int dy = 0; dy < 3; dy++)
        #pragma unroll
        for (int dx = 0; dx < 3; dx++) {
            bool xv = (unsigned)(x + 1 - dx) < (unsigned)WW;
            if (xv && (unsigned)(y0 + 1 - dy) < (unsigned)HH) pm0 |= 1u << (dy * 3 + dx);
            if (xv && (unsigned)(y0 + 2 - dy) < (unsigned)HH) pm1 |= 1u << (dy * 3 + dx);
        }
    bool full0 = (pm0 == 0x1FFu), full1 = (pm1 == 0x1FFu);

    float* Sout0 = g_E + (size_t)b * MM * MM + (size_t)(y0 * WW + x) * MM;
    float* Sout1 = Sout0 + (size_t)WW * MM;

    for (int q = tid; q < MM; q += 256) {
        int qy = q / WW, qx = q - qy * WW;
        int cb = qy * HC + qx;
        const float* p0 = base0 + cb;
        const float* p1 = base1 + cb;
        float s0 = 0.f, s1 = 0.f;
        if (full0 && full1 && qy >= 2 && qy <= 45 && qx >= 2 && qx <= 45) {
            #pragma unroll
            for (int dy = 0; dy < 3; dy++)
                #pragma unroll
                for (int dx = 0; dx < 3; dx++) {
                    int off = -(dy * (WW * CC + HC) + dx * (CC + 1));
                    s0 += p0[off];
                    s1 += p1[off];
                }
        } else {
            unsigned pq = 0;
            #pragma unroll
            for (int dy = 0; dy < 3; dy++)
                #pragma unroll
                for (int dx = 0; dx < 3; dx++)
                    if ((unsigned)(qy - dy) < (unsigned)HC &&
                        (unsigned)(qx - dx) < (unsigned)HC)
                        pq |= 1u << (dy * 3 + dx);
            unsigned e0 = pm0 & pq, e1 = pm1 & pq;
            #pragma unroll
            for (int dy = 0; dy < 3; dy++)
                #pragma unroll
                for (int dx = 0; dx < 3; dx++) {
                    int bit = dy * 3 + dx;
                    int off = -(dy * (WW * CC + HC) + dx * (CC + 1));
                    if (e0 & (1u << bit)) s0 += p0[off];
                    if (e1 & (1u << bit)) s1 += p1[off];
                }
        }
        Sout0[q] = s0;
        Sout1[q] = s1;
    }
}

// ---------------------------------------------------------------------------
// gemm_acl: acl[m,d] = sum_q S[m,q] * bg[q,d]; ACL = bg + acl/9*(1-mask).
// BM=64, BN=32, BK=16, 128 threads, 4x4 micro, double-buffered + reg prefetch.
#define NKT (MM / 16)   // 144 k-tiles
__global__ __launch_bounds__(128) void gemm_acl_kernel(const float* __restrict__ mask) {
    __shared__ float As[2][16][68];
    __shared__ float Bs[2][16][32];
    int b  = blockIdx.z;
    int m0 = blockIdx.x * 64;
    int n0 = blockIdx.y * 32;
    int tid = threadIdx.x;
    int ty = tid >> 3, tx = tid & 7;

    int ar0 = tid >> 2,        akc0 = (tid & 3) * 4;
    int ar1 = (tid + 128) >> 2, akc1 = (tid & 3) * 4;
    int bkr = tid >> 3, bcc = (tid & 7) * 4;

    const float* Sb  = g_E  + (size_t)b * MM * MM + (size_t)m0 * MM;
    const float* bgb = g_bg + (size_t)b * MM * DD;

    float4 pa0, pa1, pb;
    pa0 = *(const float4*)(Sb + (size_t)ar0 * MM + akc0);
    pa1 = *(const float4*)(Sb + (size_t)ar1 * MM + akc1);
    pb  = *(const float4*)(bgb + bkr * DD + n0 + bcc);
    As[0][akc0 + 0][ar0] = pa0.x; As[0][akc0 + 1][ar0] = pa0.y;
    As[0][akc0 + 2][ar0] = pa0.z; As[0][akc0 + 3][ar0] = pa0.w;
    As[0][akc1 + 0][ar1] = pa1.x; As[0][akc1 + 1][ar1] = pa1.y;
    As[0][akc1 + 2][ar1] = pa1.z; As[0][akc1 + 3][ar1] = pa1.w;
    *(float4*)(&Bs[0][bkr][bcc]) = pb;
    __syncthreads();

    float acc[4][4];
    #pragma unroll
    for (int i = 0; i < 4; i++)
        #pragma unroll
        for (int j = 0; j < 4; j++) acc[i][j] = 0.f;

    for (int t = 0; t < NKT; t++) {
        int cur = t & 1;
        if (t + 1 < NKT) {
            int k0 = (t + 1) * 16;
            pa0 = *(const float4*)(Sb + (size_t)ar0 * MM + k0 + akc0);
            pa1 = *(const float4*)(Sb + (size_t)ar1 * MM + k0 + akc1);
            pb  = *(const float4*)(bgb + (k0 + bkr) * DD + n0 + bcc);
        }
        #pragma unroll
        for (int k = 0; k < 16; k++) {
            float4 a4 = *(const float4*)(&As[cur][k][ty * 4]);
            float4 b4 = *(const float4*)(&Bs[cur][k][tx * 4]);
            float av[4] = {a4.x, a4.y, a4.z, a4.w};
            float bv[4] = {b4.x, b4.y, b4.z, b4.w};
            #pragma unroll
            for (int i = 0; i < 4; i++)
                #pragma unroll
                for (int j = 0; j < 4; j++) acc[i][j] += av[i] * bv[j];
        }
        if (t + 1 < NKT) {
            int nxt = 1 - cur;
            As[nxt][akc0 + 0][ar0] = pa0.x; As[nxt][akc0 + 1][ar0] = pa0.y;
            As[nxt][akc0 + 2][ar0] = pa0.z; As[nxt][akc0 + 3][ar0] = pa0.w;
            As[nxt][akc1 + 0][ar1] = pa1.x; As[nxt][akc1 + 1][ar1] = pa1.y;
            As[nxt][akc1 + 2][ar1] = pa1.z; As[nxt][akc1 + 3][ar1] = pa1.w;
            *(float4*)(&Bs[nxt][bkr][bcc]) = pb;
        }
        __syncthreads();
    }

    #pragma unroll
    for (int i = 0; i < 4; i++) {
        int rowm = b * MM + m0 + ty * 4 + i;
        float om = (1.f - mask[rowm]) * (1.f / 9.f);
        float4 v;
        int idx = rowm * DD + n0 + tx * 4;
        v.x = g_bg[idx + 0] + acc[i][0] * om;
        v.y = g_bg[idx + 1] + acc[i][1] * om;
        v.z = g_bg[idx + 2] + acc[i][2] * om;
        v.w = g_bg[idx + 3] + acc[i][3] * om;
        *(float4*)(&g_ACL[idx]) = v;
    }
}

// ---------------------------------------------------------------------------
// Final: out = elu(concat(g_in, ACL) @ W2 + b2).  4 rows x 64 cols per block.
__global__ __launch_bounds__(256) void final_kernel(const float* __restrict__ gin,
                                                    const float* __restrict__ W2,
                                                    const float* __restrict__ b2,
                                                    float* __restrict__ out) {
    __shared__ float sA[4][128];
    int r0 = blockIdx.x * 4;
    int tid = threadIdx.x;
    for (int idx = tid; idx < 512; idx += 256) {
        int r = idx >> 7, k = idx & 127;
        int row = r0 + r;
        sA[r][k] = (k < DD) ? gin[row * DD + k] : g_ACL[row * DD + (k - DD)];
    }
    __syncthreads();
    int r = tid >> 6, d = tid & 63;
    int row = r0 + r;
    float acc = b2[d];
    #pragma unroll 8
    for (int k = 0; k < 128; k++) acc += sA[r][k] * W2[k * DD + d];
    out[row * DD + d] = (acc > 0.f) ? acc : expm1f(acc);
}

// ---------------------------------------------------------------------------
extern "C" void kernel_launch(void* const* d_in, const int* in_sizes, int n_in,
                              void* d_out, int out_size) {
    const float* gin  = (const float*)d_in[0];
    const float* mask = (const float*)d_in[1];
    const float* W2   = (const float*)d_in[2];
    const float* b2   = (const float*)d_in[3];
    float* out = (float*)d_out;

    prep_kernel<<<BATCH * MM, DD>>>(gin, mask);
    int tot = BATCH * MM + BATCH * CC;
    boxsum_kernel<<<(tot + 255) / 256, 256>>>();
    gemmE_syrk_kernel<<<dim3(NPAIR, BATCH), 256>>>(gin, mask);
    ds_softmax_kernel<<<BATCH * MM, 256>>>();
    s_gather_kernel<<<BATCH * MM / 2, 256>>>();
    gemm_acl_kernel<<<dim3(MM / 64, DD / 32, BATCH), 128>>>(mask);
    final_kernel<<<BATCH * MM / 4, 256>>>(gin, W2, b2, out);
}

// round 14
// speedup vs baseline: 2.0007x; 1.1309x over previous
#include <cuda_runtime.h>
#include <math.h>
#include <stddef.h>

// Problem constants
#define BATCH 4
#define HH 48
#define WW 48
#define DD 64
#define HC 46                 // valid patch grid
#define CC 2116               // HC*HC candidate patches
#define MM 2304               // HH*WW locations
#define TEMPR 50.0f

// Scratch (device globals -- no runtime allocation allowed)
static __device__ float g_E [(size_t)BATCH * MM * MM];   // E Gram, then Sc (85 MB)
static __device__ float g_DS[(size_t)BATCH * MM * CC];   // CA (78 MB)
static __device__ float g_bg [BATCH * MM * DD];          // g_in * mask
static __device__ float g_bgc[BATCH * MM * DD];          // compacted bg rows
static __device__ float g_sg [BATCH * MM];               // per-pixel sum g^2
static __device__ float g_sbg[BATCH * MM];               // per-pixel sum bg^2
static __device__ float g_wwd[BATCH * MM];               // 3x3 box sum (same pad) of g_sg
static __device__ float g_k1d[BATCH * CC];               // 3x3 box sum (valid) of g_sbg
static __device__ float g_ACL[BATCH * MM * DD];
static __device__ int   g_qlist[BATCH * MM];             // ascending nonzero-mask pixels
static __device__ int   g_Kc [BATCH];                    // count
static __device__ int   g_Kcp[BATCH];                    // count padded to 16

// ---------------------------------------------------------------------------
// Kernel 0a: bg = g_in * mask ; per-pixel sums of squares
__global__ void prep_kernel(const float* __restrict__ gin, const float* __restrict__ mask) {
    int p = blockIdx.x;
    int d = threadIdx.x;
    float mv = mask[p];
    float g  = gin[p * DD + d];
    float bgv = g * mv;
    g_bg[p * DD + d] = bgv;
    __shared__ float s1[DD];
    __shared__ float s2[DD];
    s1[d] = g * g;
    s2[d] = bgv * bgv;
    __syncthreads();
    #pragma unroll
    for (int s = 32; s > 0; s >>= 1) {
        if (d < s) { s1[d] += s1[d + s]; s2[d] += s2[d + s]; }
        __syncthreads();
    }
    if (d == 0) { g_sg[p] = s1[0]; g_sbg[p] = s2[0]; }
}

// Kernel 0b: box sums -> wwd (same pad) and k1d (valid)
__global__ void boxsum_kernel() {
    int idx = blockIdx.x * blockDim.x + threadIdx.x;
    if (idx < BATCH * MM) {
        int b = idx / MM, m = idx - b * MM;
        int y = m / WW, x = m - y * WW;
        float s = 0.f;
        #pragma unroll
        for (int dy = 0; dy < 3; dy++)
            #pragma unroll
            for (int dx = 0; dx < 3; dx++) {
                int yy = y + dy - 1, xx = x + dx - 1;
                if (yy >= 0 && yy < HH && xx >= 0 && xx < WW)
                    s += g_sg[(b * HH + yy) * WW + xx];
            }
        g_wwd[idx] = s;
    } else if (idx < BATCH * MM + BATCH * CC) {
        int id2 = idx - BATCH * MM;
        int b = id2 / CC, j = id2 - b * CC;
        int jy = j / HC, jx = j - jy * HC;
        float s = 0.f;
        #pragma unroll
        for (int dy = 0; dy < 3; dy++)
            #pragma unroll
            for (int dx = 0; dx < 3; dx++)
                s += g_sbg[(b * HH + jy + dy) * WW + jx + dx];
        g_k1d[id2] = s;
    }
}

// ---------------------------------------------------------------------------
// scan: deterministic block scan (no atomics) -> qlist of nonzero-mask pixels
__global__ __launch_bounds__(256) void scan_kernel(const float* __restrict__ mask) {
    int b = blockIdx.x;
    int tid = threadIdx.x;
    int lane = tid & 31, wid = tid >> 5;
    __shared__ int wsum[8];
    __shared__ int sbase;
    if (tid == 0) sbase = 0;
    __syncthreads();
    for (int c0 = 0; c0 < MM; c0 += 256) {
        int q = c0 + tid;
        int f = (mask[b * MM + q] != 0.f) ? 1 : 0;
        int incl = f;
        #pragma unroll
        for (int o = 1; o < 32; o <<= 1) {
            int t = __shfl_up_sync(0xffffffffu, incl, o);
            if (lane >= o) incl += t;
        }
        if (lane == 31) wsum[wid] = incl;
        __syncthreads();
        int woff = 0;
        #pragma unroll
        for (int w = 0; w < 8; w++) if (w < wid) woff += wsum[w];
        int excl = sbase + woff + incl - f;
        if (f) g_qlist[b * MM + excl] = q;
        __syncthreads();
        if (tid == 0) {
            int tot = 0;
            #pragma unroll
            for (int w = 0; w < 8; w++) tot += wsum[w];
            sbase += tot;
        }
        __syncthreads();
    }
    if (tid == 0) {
        g_Kc[b]  = sbase;
        g_Kcp[b] = (sbase + 15) & ~15;
    }
}

// compact bg rows: bgc[b][k][:] = bg[b][qlist[k]][:], zero for pad rows.
__global__ void compact_bg_kernel() {
    int b = blockIdx.y, k = blockIdx.x, d = threadIdx.x;
    if (k >= g_Kcp[b]) return;
    float v = 0.f;
    if (k < g_Kc[b]) {
        int q = g_qlist[b * MM + k];
        v = g_bg[(b * MM + q) * DD + d];
    }
    g_bgc[(b * MM + k) * DD + d] = v;
}

// ---------------------------------------------------------------------------
// gemmE (SYRK): G = gin @ gin^T symmetric; E[p,q] = G[p,q]*mask[q].
// K=64 staged into smem in ONE shot -> single sync.  Mirror tile staged
// through smem (overlaid on As/Bs) for coalesced writes.
#define NTILE (MM / 64)                       // 36
#define NPAIR (NTILE * (NTILE + 1) / 2)       // 666
__global__ __launch_bounds__(256) void gemmE_syrk_kernel(const float* __restrict__ gin,
                                                         const float* __restrict__ mask) {
    __shared__ float buf[2 * 64 * 64];
    float (*As)[64] = (float(*)[64])buf;
    float (*Bs)[64] = (float(*)[64])(buf + 64 * 64);

    int b = blockIdx.y;
    int t = blockIdx.x;
    int i = (int)((sqrtf(8.f * t + 1.f) - 1.f) * 0.5f);
    while ((i + 1) * (i + 2) / 2 <= t) i++;
    while (i * (i + 1) / 2 > t) i--;
    int j = t - i * (i + 1) / 2;
    int p0 = i * 64;
    int q0 = j * 64;

    int tid = threadIdx.x;
    int lk = (tid & 3) * 4;
    int lr = tid >> 2;
    int ty = tid >> 4, tx = tid & 15;

    const float* A = gin + (size_t)b * MM * DD;

    #pragma unroll
    for (int k0 = 0; k0 < DD; k0 += 16) {
        float4 va = *(const float4*)(A + (p0 + lr) * DD + k0 + lk);
        As[k0 + lk + 0][lr] = va.x; As[k0 + lk + 1][lr] = va.y;
        As[k0 + lk + 2][lr] = va.z; As[k0 + lk + 3][lr] = va.w;
        float4 vb = *(const float4*)(A + (q0 + lr) * DD + k0 + lk);
        Bs[k0 + lk + 0][lr] = vb.x; Bs[k0 + lk + 1][lr] = vb.y;
        Bs[k0 + lk + 2][lr] = vb.z; Bs[k0 + lk + 3][lr] = vb.w;
    }
    __syncthreads();

    float acc[4][4];
    #pragma unroll
    for (int ii = 0; ii < 4; ii++)
        #pragma unroll
        for (int jj = 0; jj < 4; jj++) acc[ii][jj] = 0.f;

    #pragma unroll 8
    for (int k = 0; k < DD; k++) {
        float4 a4 = *(const float4*)(&As[k][ty * 4]);
        float4 b4 = *(const float4*)(&Bs[k][tx * 4]);
        float av[4] = {a4.x, a4.y, a4.z, a4.w};
        float bv[4] = {b4.x, b4.y, b4.z, b4.w};
        #pragma unroll
        for (int ii = 0; ii < 4; ii++)
            #pragma unroll
            for (int jj = 0; jj < 4; jj++) acc[ii][jj] += av[ii] * bv[jj];
    }

    float* Eb = g_E + (size_t)b * MM * MM;
    const float* mb = mask + b * MM;

    float mq[4];
    #pragma unroll
    for (int c = 0; c < 4; c++) mq[c] = mb[q0 + tx * 4 + c];
    #pragma unroll
    for (int r = 0; r < 4; r++) {
        float4 v;
        v.x = acc[r][0] * mq[0]; v.y = acc[r][1] * mq[1];
        v.z = acc[r][2] * mq[2]; v.w = acc[r][3] * mq[3];
        *(float4*)(Eb + (size_t)(p0 + ty * 4 + r) * MM + q0 + tx * 4) = v;
    }

    if (i != j) {
        float (*sT)[65] = (float(*)[65])buf;
        float mp[4];
        #pragma unroll
        for (int r = 0; r < 4; r++) mp[r] = mb[p0 + ty * 4 + r];
        __syncthreads();
        #pragma unroll
        for (int r = 0; r < 4; r++)
            #pragma unroll
            for (int c = 0; c < 4; c++)
                sT[tx * 4 + c][ty * 4 + r] = acc[r][c] * mp[r];
        __syncthreads();
        #pragma unroll
        for (int rr = 0; rr < 4; rr++) {
            int idx = tid + 256 * rr;
            int row = idx >> 4;
            int ch  = idx & 15;
            float4 v;
            v.x = sT[row][ch * 4 + 0]; v.y = sT[row][ch * 4 + 1];
            v.z = sT[row][ch * 4 + 2]; v.w = sT[row][ch * 4 + 3];
            *(float4*)(Eb + (size_t)(q0 + row) * MM + p0 + ch * 4) = v;
        }
    }
}

// ---------------------------------------------------------------------------
__device__ __forceinline__ float block_sum256(float v, float* red) {
    int tid = threadIdx.x;
    #pragma unroll
    for (int o = 16; o > 0; o >>= 1) v += __shfl_xor_sync(0xffffffffu, v, o);
    __syncthreads();
    if ((tid & 31) == 0) red[tid >> 5] = v;
    __syncthreads();
    float tot = red[0] + red[1] + red[2] + red[3] + red[4] + red[5] + red[6] + red[7];
    return tot;
}

// ---------------------------------------------------------------------------
// Fused DS + tanh-normalized softmax.  One CTA per output row m.
__global__ __launch_bounds__(256) void ds_softmax_kernel() {
    __shared__ float red[8];
    int row = blockIdx.x;
    int b = row / MM, m = row - b * MM;
    int y = m / WW, x = m - y * WW;
    int tid = threadIdx.x;

    const float* Eb = g_E + (size_t)b * MM * MM;
    const float* base = Eb + (ptrdiff_t)((y - 1) * WW + (x - 1)) * MM;
    float wv = g_wwd[row];
    const float* k1 = g_k1d + b * CC;

    bool tvy[3], tvx[3];
    #pragma unroll
    for (int t = 0; t < 3; t++) {
        tvy[t] = (unsigned)(y + t - 1) < (unsigned)HH;
        tvx[t] = (unsigned)(x + t - 1) < (unsigned)WW;
    }
    bool interior = tvy[0] && tvy[2] && tvx[0] && tvx[2];

    float v[9];
    float s = 0.f;

    if (interior) {
        #pragma unroll
        for (int i = 0; i < 9; i++) {
            int n = tid + 256 * i;
            if (n < CC) {
                int jy = n / HC, jx = n - jy * HC;
                const float* p = base + (jy * WW + jx);
                float cs = 0.f;
                #pragma unroll
                for (int dy = 0; dy < 3; dy++)
                    #pragma unroll
                    for (int dx = 0; dx < 3; dx++)
                        cs += p[(dy * WW + dx) * (MM + 1)];
                float val = fmaf(-2.f, cs, k1[n] + wv);
                v[i] = val;
                s += val;
            } else v[i] = 0.f;
        }
    } else {
        #pragma unroll
        for (int i = 0; i < 9; i++) {
            int n = tid + 256 * i;
            if (n < CC) {
                int jy = n / HC, jx = n - jy * HC;
                const float* p = base + (jy * WW + jx);
                float cs = 0.f;
                #pragma unroll
                for (int dy = 0; dy < 3; dy++)
                    #pragma unroll
                    for (int dx = 0; dx < 3; dx++)
                        if (tvy[dy] && tvx[dx])
                            cs += p[(dy * WW + dx) * (MM + 1)];
                float val = fmaf(-2.f, cs, k1[n] + wv);
                v[i] = val;
                s += val;
            } else v[i] = 0.f;
        }
    }

    float mu = block_sum256(s, red) * (1.0f / CC);

    float s2 = 0.f;
    #pragma unroll
    for (int i = 0; i < 9; i++) {
        int n = tid + 256 * i;
        if (n < CC) { float d = v[i] - mu; s2 = fmaf(d, d, s2); }
    }
    float isd = rsqrtf(block_sum256(s2, red) * (1.0f / CC));

    float se = 0.f;
    #pragma unroll
    for (int i = 0; i < 9; i++) {
        int n = tid + 256 * i;
        if (n < CC) {
            float w = (v[i] - mu) * isd;
            float u = __expf(2.f * w);
            float e = __expf(__fdividef(100.f, u + 1.f) - 50.f);
            v[i] = e;
            se += e;
        }
    }
    float inv = 1.0f / block_sum256(se, red);

    float* rp = g_DS + (size_t)row * CC;
    #pragma unroll
    for (int i = 0; i < 9; i++) {
        int n = tid + 256 * i;
        if (n < CC) rp[n] = v[i] * inv;
    }
}

// ---------------------------------------------------------------------------
// S gather (COMPACTED): Sc[m,k] for k in [0,Kcp), q = qlist[k] ascending.
// Paired rows (y, y+1) per CTA for CA line reuse.  Pad cols -> 0.
__global__ __launch_bounds__(256) void s_gather_kernel() {
    int pid = blockIdx.x;
    int b = pid / (MM / 2);
    int mp = pid - b * (MM / 2);
    int yh = mp / WW, x = mp - yh * WW;
    int y0 = yh * 2;
    int tid = threadIdx.x;
    int Kc = g_Kc[b], Kcp = g_Kcp[b];

    const float* CAb = g_DS + (size_t)b * MM * CC;
    const float* base0 = CAb + (ptrdiff_t)((y0 + 1) * WW + (x + 1)) * CC;
    const float* base1 = base0 + (ptrdiff_t)WW * CC;
    const int* ql = g_qlist + b * MM;

    unsigned pm0 = 0, pm1 = 0;
    #pragma unroll
    for (int dy = 0; dy < 3; dy++)
        #pragma unroll
        for (int dx = 0; dx < 3; dx++) {
            bool xv = (unsigned)(x + 1 - dx) < (unsigned)WW;
            if (xv && (unsigned)(y0 + 1 - dy) < (unsigned)HH) pm0 |= 1u << (dy * 3 + dx);
            if (xv && (unsigned)(y0 + 2 - dy) < (unsigned)HH) pm1 |= 1u << (dy * 3 + dx);
        }
    bool full0 = (pm0 == 0x1FFu), full1 = (pm1 == 0x1FFu);

    float* Sout0 = g_E + (size_t)b * MM * MM + (size_t)(y0 * WW + x) * MM;
    float* Sout1 = Sout0 + (size_t)WW * MM;

    for (int k = tid; k < Kcp; k += 256) {
        float s0 = 0.f, s1 = 0.f;
        if (k < Kc) {
            int q = ql[k];
            int qy = q / WW, qx = q - qy * WW;
            int cb = qy * HC + qx;
            const float* p0 = base0 + cb;
            const float* p1 = base1 + cb;
            if (full0 && full1 && qy >= 2 && qy <= 45 && qx >= 2 && qx <= 45) {
                #pragma unroll
                for (int dy = 0; dy < 3; dy++)
                    #pragma unroll
                    for (int dx = 0; dx < 3; dx++) {
                        int off = -(dy * (WW * CC + HC) + dx * (CC + 1));
                        s0 += p0[off];
                        s1 += p1[off];
                    }
            } else {
                unsigned pq = 0;
                #pragma unroll
                for (int dy = 0; dy < 3; dy++)
                    #pragma unroll
                    for (int dx = 0; dx < 3; dx++)
                        if ((unsigned)(qy - dy) < (unsigned)HC &&
                            (unsigned)(qx - dx) < (unsigned)HC)
                            pq |= 1u << (dy * 3 + dx);
                unsigned e0 = pm0 & pq, e1 = pm1 & pq;
                #pragma unroll
                for (int dy = 0; dy < 3; dy++)
                    #pragma unroll
                    for (int dx = 0; dx < 3; dx++) {
                        int bit = dy * 3 + dx;
                        int off = -(dy * (WW * CC + HC) + dx * (CC + 1));
                        if (e0 & (1u << bit)) s0 += p0[off];
                        if (e1 & (1u << bit)) s1 += p1[off];
                    }
            }
        }
        Sout0[k] = s0;
        Sout1[k] = s1;
    }
}

// ---------------------------------------------------------------------------
// gemm_acl (compacted K): acl[m,d] = sum_k Sc[m,k] * bgc[k,d], k < Kcp[b].
// BM=64, BN=32, BK=16, 128 threads, 4x4 micro, double-buffered + reg prefetch.
__global__ __launch_bounds__(128) void gemm_acl_kernel(const float* __restrict__ mask) {
    __shared__ float As[2][16][68];
    __shared__ float Bs[2][16][32];
    int b  = blockIdx.z;
    int m0 = blockIdx.x * 64;
    int n0 = blockIdx.y * 32;
    int tid = threadIdx.x;
    int ty = tid >> 3, tx = tid & 7;
    int nkt = g_Kcp[b] >> 4;

    int ar0 = tid >> 2,        akc0 = (tid & 3) * 4;
    int ar1 = (tid + 128) >> 2, akc1 = (tid & 3) * 4;
    int bkr = tid >> 3, bcc = (tid & 7) * 4;

    const float* Sb  = g_E   + (size_t)b * MM * MM + (size_t)m0 * MM;
    const float* bgc = g_bgc + (size_t)b * MM * DD;

    float acc[4][4];
    #pragma unroll
    for (int i = 0; i < 4; i++)
        #pragma unroll
        for (int j = 0; j < 4; j++) acc[i][j] = 0.f;

    if (nkt > 0) {
        float4 pa0, pa1, pb;
        pa0 = *(const float4*)(Sb + (size_t)ar0 * MM + akc0);
        pa1 = *(const float4*)(Sb + (size_t)ar1 * MM + akc1);
        pb  = *(const float4*)(bgc + bkr * DD + n0 + bcc);
        As[0][akc0 + 0][ar0] = pa0.x; As[0][akc0 + 1][ar0] = pa0.y;
        As[0][akc0 + 2][ar0] = pa0.z; As[0][akc0 + 3][ar0] = pa0.w;
        As[0][akc1 + 0][ar1] = pa1.x; As[0][akc1 + 1][ar1] = pa1.y;
        As[0][akc1 + 2][ar1] = pa1.z; As[0][akc1 + 3][ar1] = pa1.w;
        *(float4*)(&Bs[0][bkr][bcc]) = pb;
        __syncthreads();

        for (int t = 0; t < nkt; t++) {
            int cur = t & 1;
            if (t + 1 < nkt) {
                int k0 = (t + 1) * 16;
                pa0 = *(const float4*)(Sb + (size_t)ar0 * MM + k0 + akc0);
                pa1 = *(const float4*)(Sb + (size_t)ar1 * MM + k0 + akc1);
                pb  = *(const float4*)(bgc + (k0 + bkr) * DD + n0 + bcc);
            }
            #pragma unroll
            for (int k = 0; k < 16; k++) {
                float4 a4 = *(const float4*)(&As[cur][k][ty * 4]);
                float4 b4 = *(const float4*)(&Bs[cur][k][tx * 4]);
                float av[4] = {a4.x, a4.y, a4.z, a4.w};
                float bv[4] = {b4.x, b4.y, b4.z, b4.w};
                #pragma unroll
                for (int i = 0; i < 4; i++)
                    #pragma unroll
                    for (int j = 0; j < 4; j++) acc[i][j] += av[i] * bv[j];
            }
            if (t + 1 < nkt) {
                int nxt = 1 - cur;
                As[nxt][akc0 + 0][ar0] = pa0.x; As[nxt][akc0 + 1][ar0] = pa0.y;
                As[nxt][akc0 + 2][ar0] = pa0.z; As[nxt][akc0 + 3][ar0] = pa0.w;
                As[nxt][akc1 + 0][ar1] = pa1.x; As[nxt][akc1 + 1][ar1] = pa1.y;
                As[nxt][akc1 + 2][ar1] = pa1.z; As[nxt][akc1 + 3][ar1] = pa1.w;
                *(float4*)(&Bs[nxt][bkr][bcc]) = pb;
            }
            __syncthreads();
        }
    }

    #pragma unroll
    for (int i = 0; i < 4; i++) {
        int rowm = b * MM + m0 + ty * 4 + i;
        float om = (1.f - mask[rowm]) * (1.f / 9.f);
        float4 v;
        int idx = rowm * DD + n0 + tx * 4;
        v.x = g_bg[idx + 0] + acc[i][0] * om;
        v.y = g_bg[idx + 1] + acc[i][1] * om;
        v.z = g_bg[idx + 2] + acc[i][2] * om;
        v.w = g_bg[idx + 3] + acc[i][3] * om;
        *(float4*)(&g_ACL[idx]) = v;
    }
}

// ---------------------------------------------------------------------------
// Final: out = elu(concat(g_in, ACL) @ W2 + b2).  4 rows x 64 cols per block.
__global__ __launch_bounds__(256) void final_kernel(const float* __restrict__ gin,
                                                    const float* __restrict__ W2,
                                                    const float* __restrict__ b2,
                                                    float* __restrict__ out) {
    __shared__ float sA[4][128];
    int r0 = blockIdx.x * 4;
    int tid = threadIdx.x;
    for (int idx = tid; idx < 512; idx += 256) {
        int r = idx >> 7, k = idx & 127;
        int row = r0 + r;
        sA[r][k] = (k < DD) ? gin[row * DD + k] : g_ACL[row * DD + (k - DD)];
    }
    __syncthreads();
    int r = tid >> 6, d = tid & 63;
    int row = r0 + r;
    float acc = b2[d];
    #pragma unroll 8
    for (int k = 0; k < 128; k++) acc += sA[r][k] * W2[k * DD + d];
    out[row * DD + d] = (acc > 0.f) ? acc : expm1f(acc);
}

// ---------------------------------------------------------------------------
extern "C" void kernel_launch(void* const* d_in, const int* in_sizes, int n_in,
                              void* d_out, int out_size) {
    const float* gin  = (const float*)d_in[0];
    const float* mask = (const float*)d_in[1];
    const float* W2   = (const float*)d_in[2];
    const float* b2   = (const float*)d_in[3];
    float* out = (float*)d_out;

    prep_kernel<<<BATCH * MM, DD>>>(gin, mask);
    int tot = BATCH * MM + BATCH * CC;
    boxsum_kernel<<<(tot + 255) / 256, 256>>>();
    scan_kernel<<<BATCH, 256>>>(mask);
    compact_bg_kernel<<<dim3(MM, BATCH), DD>>>();
    gemmE_syrk_kernel<<<dim3(NPAIR, BATCH), 256>>>(gin, mask);
    ds_softmax_kernel<<<BATCH * MM, 256>>>();
    s_gather_kernel<<<BATCH * MM / 2, 256>>>();
    gemm_acl_kernel<<<dim3(MM / 64, DD / 32, BATCH), 128>>>(mask);
    final_kernel<<<BATCH * MM / 4, 256>>>(gin, W2, b2, out);
}